// round 13
// baseline (speedup 1.0000x reference)
#include <cuda_runtime.h>
#include <cuda_bf16.h>
#include <math.h>

#define NI 32     // images
#define NB 128    // captions
#define RR 128    // reduced channels
#define LL 1024   // latent
#define TT 64     // initial time
#define CBS 4     // caption batch per CTA (conv, c1) — wave-quantization tuned

typedef unsigned long long u64;
typedef unsigned int u32;
typedef unsigned short u16;

// ---------------- warp mma.sync bf16 + ldmatrix (sm_75/80 baseline PTX) -------
__device__ __forceinline__ void mma16816(float c[4], const u32 a[4], const u32 b[2]) {
    asm volatile("mma.sync.aligned.m16n8k16.row.col.f32.bf16.bf16.f32 "
                 "{%0,%1,%2,%3}, {%4,%5,%6,%7}, {%8,%9}, {%0,%1,%2,%3};"
                 : "+f"(c[0]), "+f"(c[1]), "+f"(c[2]), "+f"(c[3])
                 : "r"(a[0]), "r"(a[1]), "r"(a[2]), "r"(a[3]), "r"(b[0]), "r"(b[1]));
}
__device__ __forceinline__ void ldsm_x4(u32& r0, u32& r1, u32& r2, u32& r3, u32 addr) {
    asm volatile("ldmatrix.sync.aligned.m8n8.x4.shared.b16 {%0,%1,%2,%3}, [%4];"
                 : "=r"(r0), "=r"(r1), "=r"(r2), "=r"(r3) : "r"(addr));
}
__device__ __forceinline__ void bsplit(float v, u16& h, u16& l) {
    __nv_bfloat16 hb = __float2bfloat16(v);
    __nv_bfloat16 lb = __float2bfloat16(v - __bfloat162float(hb));
    h = __bfloat16_as_ushort(hb); l = __bfloat16_as_ushort(lb);
}
__device__ __forceinline__ u32 pk16(u16 a, u16 b) { return (u32)a | ((u32)b << 16); }

// ---------------- device scratch (static globals; no allocation) ----------------
__device__ float  g_img_global[NI*LL];
__device__ float  g_inorm[NI];
__device__ float  g_img_vec[NI*RR];
__device__ float  g_kernT[NI*2*4*64*64];               // [(i2j)][g*2+k][o'][ci]
__device__ float  g_caT[2*4*64*64];                    // [j][g*2+k][row][ci]
__device__ double g_stats[2*NI*512];                   // per-j per-image per-channel sum/sumsq
__device__ float  g_h[(size_t)NI*NB*64*256];           // conv outputs, [ib][t][256ch]
__device__ __align__(16) u16 g_crh[NB*64*128];         // cap_red split hi, [b][t][c]
__device__ __align__(16) u16 g_crl[NB*64*128];
__device__ __align__(16) u16 g_xh[(size_t)NI*NB*64*128];  // x split hi, [ib][t][c]
__device__ __align__(16) u16 g_xl[(size_t)NI*NB*64*128];
__device__ float  g_y[(size_t)NI*NB*1024];             // max-pooled pre-norm

// ---------------- stage 1: image prep (mean, norm, hypernet base) ----------------
__global__ __launch_bounds__(256) void k_img_prep(const float* __restrict__ img_embed,
                                                  const float* __restrict__ W_ri,
                                                  const float* __restrict__ b_ri) {
    __shared__ float gsh[LL];
    __shared__ float red[256];
    int i = blockIdx.x, tid = threadIdx.x;
    float ssq = 0.f;
    for (int c = tid; c < LL; c += 256) {
        float s = 0.f;
        #pragma unroll
        for (int t = 0; t < 36; t++) s += img_embed[((size_t)i*36 + t)*LL + c];
        s *= (1.0f/36.0f);
        gsh[c] = s;
        g_img_global[i*LL + c] = s;
        ssq += s*s;
    }
    red[tid] = ssq; __syncthreads();
    for (int s = 128; s > 0; s >>= 1) { if (tid < s) red[tid] += red[tid+s]; __syncthreads(); }
    if (tid == 0) g_inorm[i] = sqrtf(red[0]);
    if (tid < RR) {
        int o = tid;
        float acc = b_ri[o];
        const float* w = W_ri + (size_t)o * LL;
        for (int c = 0; c < LL; c++) acc = fmaf(w[c], gsh[c], acc);
        g_img_vec[i*RR + o] = acc;
    }
}

// ---------------- stage 2: hypernet kernel gen + weight BN, 128 CTAs --------------
__global__ __launch_bounds__(256) void k_gen(const float* __restrict__ mk_W,
                                             const float* __restrict__ mk_b,
                                             const float* __restrict__ wn_g,
                                             const float* __restrict__ wn_b) {
    extern __shared__ float sm[];
    float* base = sm;          // 128
    float* kraw = sm + 128;    // 8192
    int bx = blockIdx.x, tid = threadIdx.x;
    int i = bx >> 2, j = (bx >> 1) & 1, half = bx & 1;
    {
        int z = bx*256 + tid;
        if (z < 2*NI*512) g_stats[z] = 0.0;
    }
    if (tid < RR) base[tid] = g_img_vec[i*RR + tid];
    __syncthreads();
    int fbase = half*8192;
    for (int f = tid; f < 8192; f += 256) {
        float acc = mk_b[j*16384 + fbase + f];
        const float* w = mk_W + ((size_t)j*16384 + fbase + f)*128;
        #pragma unroll 4
        for (int c = 0; c < 128; c++) acc = fmaf(w[c], base[c], acc);
        kraw[f] = acc;
    }
    __syncthreads();
    if (tid < 64) {
        int o = half*64 + tid;
        int g = o >> 6, op = o & 63;
        const float* kr = kraw + tid*128;
        float s = 0.f, s2 = 0.f;
        for (int c = 0; c < 128; c++) { float v = kr[c]; s += v; s2 += v*v; }
        float m   = s * (1.f/128.f);
        float var = s2 * (1.f/128.f) - m*m;
        float a   = wn_g[j*RR+o] * rsqrtf(var + 1e-5f);
        float bbv = wn_b[j*RR+o] - a*m;
        float* dst = g_kernT + (size_t)(i*2+j)*16384;
        for (int cik = 0; cik < 128; cik++) {
            int ci = cik >> 1, k = cik & 1;
            dst[((g*2+k)*64 + op)*64 + ci] = fmaf(a, kr[cik], bbv);
        }
    }
}

// ---------------- stage 3: caption reduction (split-bf16 out) + ca_W transform -----
__global__ __launch_bounds__(256) void k_cap_red(const float* __restrict__ cap_embed,
                                                 const float* __restrict__ W_rt,
                                                 const float* __restrict__ b_rt,
                                                 const float* __restrict__ ca_W) {
    extern __shared__ float sm[];
    float* ce = sm;                      // [c 300][t 64]
    int b = blockIdx.x, tid = threadIdx.x;
    for (int u = b*256 + tid; u < 32768; u += NB*256) {
        int ci = u & 63, row = (u >> 6) & 63, gk = (u >> 12) & 3, j2 = u >> 14;
        int o = (gk >> 1)*64 + row, k = gk & 1;
        g_caT[j2*16384 + (gk*64 + row)*64 + ci] = ca_W[((j2*128 + o)*64 + ci)*2 + k];
    }
    for (int idx = tid; idx < 300*TT; idx += 256) {
        int c = idx >> 6, t = idx & 63;
        ce[idx] = cap_embed[(size_t)b*TT*300 + t*300 + c];
    }
    __syncthreads();
    for (int q = tid; q < RR*16; q += 256) {
        int o = q >> 4, tq = (q & 15) * 4;
        float a0 = 0.f, a1 = 0.f, a2 = 0.f, a3 = 0.f;
        const float* w = W_rt + o*300;
        for (int c = 0; c < 300; c++) {
            float wv = w[c];
            float4 x4 = *(const float4*)(ce + c*TT + tq);
            a0 = fmaf(wv, x4.x, a0); a1 = fmaf(wv, x4.y, a1);
            a2 = fmaf(wv, x4.z, a2); a3 = fmaf(wv, x4.w, a3);
        }
        float bo = b_rt[o];
        float vv[4] = {a0 + bo, a1 + bo, a2 + bo, a3 + bo};
        #pragma unroll
        for (int n = 0; n < 4; n++) {
            u16 h, l; bsplit(vv[n], h, l);
            g_crh[b*8192 + (tq + n)*128 + o] = h;
            g_crl[b*8192 + (tq + n)*128 + o] = l;
        }
    }
}

// ---------------- stage 4: grouped convs via mma.sync + ldmatrix, g-split ----------
#define CV_AH 0
#define CV_AL 36864
#define CV_BH 73728
#define CV_BL 83088
#define CV_SMEM_TOTAL 92448

template<int TOUT>
__global__ __launch_bounds__(256, 2) void k_conv_mma(int j) {
    extern __shared__ char smc[];
    u32 smb = (u32)__cvta_generic_to_shared(smc);
    int bg = blockIdx.x, i = blockIdx.y, g = blockIdx.z, tid = threadIdx.x;
    int wid = tid >> 5, lane = tid & 31, gq = lane >> 2, t4 = lane & 3;
    int warpM = wid >> 1, warpN = wid & 1;
    int mid = lane >> 3, rr8 = lane & 7;
    int aro = (mid & 1)*8 + rr8, akb = (mid >> 1)*16;
    int bro = (mid >> 1)*8 + rr8, bkb = (mid & 1)*16;

    const float* kt = g_kernT + (size_t)(i*2 + j)*16384 + g*8192;
    const float* ct = g_caT + (size_t)j*16384 + g*8192;
    for (int idx = tid; idx < 16384; idx += 256) {
        int ci = idx & 63, row = (idx >> 6) & 127, k01 = idx >> 13;
        float v = (row < 64) ? kt[(k01*64 + row)*64 + ci]
                             : ct[(k01*64 + (row - 64))*64 + ci];
        u16 h, l; bsplit(v, h, l);
        int off = (k01*128 + row)*144 + ci*2;
        *(u16*)(smc + CV_AH + off) = h;
        *(u16*)(smc + CV_AL + off) = l;
    }
    if (tid < 9) {
        *(uint4*)(smc + CV_BH + 64*144 + tid*16) = make_uint4(0,0,0,0);
        *(uint4*)(smc + CV_BL + 64*144 + tid*16) = make_uint4(0,0,0,0);
    }

    uint4 ph[2], pl[2];
    {
        int b0 = bg*CBS;
        size_t ib0 = (size_t)i*NB + b0;
        const uint4* sh = (const uint4*)((j == 0) ? (g_crh + (size_t)b0*8192) : (g_xh + ib0*8192));
        const uint4* sl = (const uint4*)((j == 0) ? (g_crl + (size_t)b0*8192) : (g_xl + ib0*8192));
        #pragma unroll
        for (int r = 0; r < 2; r++) {
            int u = tid + r*256;
            int t = u >> 3, s = u & 7;
            ph[r] = sh[t*16 + g*8 + s];
            pl[r] = sl[t*16 + g*8 + s];
        }
    }

    float st_s[2][2], st_q[2][2];
    #pragma unroll
    for (int ms = 0; ms < 2; ms++)
        #pragma unroll
        for (int hq = 0; hq < 2; hq++) { st_s[ms][hq] = 0.f; st_q[ms][hq] = 0.f; }

    for (int bs = 0; bs < CBS; bs++) {
        size_t ib = (size_t)i*NB + bg*CBS + bs;
        __syncthreads();
        #pragma unroll
        for (int r = 0; r < 2; r++) {
            int u = tid + r*256;
            int t = u >> 3, s = u & 7;
            *(uint4*)(smc + CV_BH + t*144 + s*16) = ph[r];
            *(uint4*)(smc + CV_BL + t*144 + s*16) = pl[r];
        }
        __syncthreads();
        if (bs + 1 < CBS) {
            int b2 = bg*CBS + bs + 1;
            size_t ib2 = (size_t)i*NB + b2;
            const uint4* sh = (const uint4*)((j == 0) ? (g_crh + (size_t)b2*8192) : (g_xh + ib2*8192));
            const uint4* sl = (const uint4*)((j == 0) ? (g_crl + (size_t)b2*8192) : (g_xl + ib2*8192));
            #pragma unroll
            for (int r = 0; r < 2; r++) {
                int u = tid + r*256;
                int t = u >> 3, s = u & 7;
                ph[r] = sh[t*16 + g*8 + s];
                pl[r] = sl[t*16 + g*8 + s];
            }
        }

        float C[2][4][4];
        #pragma unroll
        for (int ms = 0; ms < 2; ms++)
            #pragma unroll
            for (int ns = 0; ns < 4; ns++)
                #pragma unroll
                for (int q = 0; q < 4; q++) C[ms][ns][q] = 0.f;

        #pragma unroll
        for (int term = 0; term < 3; term++) {
            u32 Ab = smb + ((term == 1) ? CV_AL : CV_AH);
            u32 Bb = smb + ((term == 2) ? CV_BL : CV_BH);
            #pragma unroll
            for (int ks = 0; ks < 2; ks++) {
                u32 aAddr = Ab + (u32)((ks*128 + warpM*32 + aro)*144 + akb);
                u32 bAddr = Bb + (u32)((warpN*32 + ks + bro)*144 + bkb);
                #pragma unroll
                for (int kc = 0; kc < 4; kc++) {
                    u32 A[2][4], B[4][2];
                    ldsm_x4(A[0][0], A[0][1], A[0][2], A[0][3], aAddr + kc*32);
                    ldsm_x4(A[1][0], A[1][1], A[1][2], A[1][3], aAddr + 16*144 + kc*32);
                    ldsm_x4(B[0][0], B[0][1], B[1][0], B[1][1], bAddr + kc*32);
                    ldsm_x4(B[2][0], B[2][1], B[3][0], B[3][1], bAddr + 16*144 + kc*32);
                    #pragma unroll
                    for (int ms = 0; ms < 2; ms++)
                        #pragma unroll
                        for (int ns = 0; ns < 4; ns++)
                            mma16816(C[ms][ns], A[ms], B[ns]);
                }
            }
        }

        float* hp = g_h + ib*16384;
        #pragma unroll
        for (int ms = 0; ms < 2; ms++) {
            int r0 = warpM*32 + ms*16 + gq;
            int r1 = r0 + 8;
            int chA = (r0 < 64) ? (g*64 + r0) : (128 + g*64 + r0 - 64);
            int chB = (r1 < 64) ? (g*64 + r1) : (128 + g*64 + r1 - 64);
            #pragma unroll
            for (int ns = 0; ns < 4; ns++) {
                int tg = warpN*32 + ns*8 + t4*2;
                if (tg < TOUT) {
                    float v0 = C[ms][ns][0], v2 = C[ms][ns][2];
                    hp[tg*256 + chA] = v0;
                    hp[tg*256 + chB] = v2;
                    st_s[ms][0] += v0; st_q[ms][0] += v0*v0;
                    st_s[ms][1] += v2; st_q[ms][1] += v2*v2;
                }
                if (tg + 1 < TOUT) {
                    float v1 = C[ms][ns][1], v3 = C[ms][ns][3];
                    hp[(tg+1)*256 + chA] = v1;
                    hp[(tg+1)*256 + chB] = v3;
                    st_s[ms][0] += v1; st_q[ms][0] += v1*v1;
                    st_s[ms][1] += v3; st_q[ms][1] += v3*v3;
                }
            }
        }
    }
    double* st = g_stats + ((size_t)j*NI + i)*512;
    #pragma unroll
    for (int ms = 0; ms < 2; ms++)
        #pragma unroll
        for (int hq = 0; hq < 2; hq++) {
            float s = st_s[ms][hq], q = st_q[ms][hq];
            s += __shfl_xor_sync(0xffffffffu, s, 1);
            s += __shfl_xor_sync(0xffffffffu, s, 2);
            q += __shfl_xor_sync(0xffffffffu, q, 1);
            q += __shfl_xor_sync(0xffffffffu, q, 2);
            if (t4 == 0) {
                int r = warpM*32 + ms*16 + gq + hq*8;
                int ch = (r < 64) ? (g*64 + r) : (128 + g*64 + r - 64);
                atomicAdd(st + ch*2,     (double)s);
                atomicAdd(st + ch*2 + 1, (double)q);
            }
        }
}

// ---------------- stage 5: BN+ReLU + c1 via mma.sync + ldmatrix --------------------
#define C1_WH 0
#define C1_WL 67584
#define C1_BH 135168
#define C1_BL 168960
#define C1_AB 202752
#define C1_SMEM_TOTAL 204800

template<int TOUT>
__global__ __launch_bounds__(256) void k_c1_mma(const float* __restrict__ bn_g,
                                                const float* __restrict__ bn_b,
                                                const float* __restrict__ c1_b,
                                                const float* __restrict__ c1_W, int j) {
    extern __shared__ char smc[];
    u32 smb = (u32)__cvta_generic_to_shared(smc);
    float* aa = (float*)(smc + C1_AB);
    float* bb = aa + 256;
    int bg = blockIdx.x, i = blockIdx.y, tid = threadIdx.x;
    int wid = tid >> 5, lane = tid & 31, g = lane >> 2, t4 = lane & 3;
    int warpM = wid >> 1, warpN = wid & 1;
    int mid = lane >> 3, rr8 = lane & 7;
    int aro = (mid & 1)*8 + rr8, akb = (mid >> 1)*16;
    int bro = (mid >> 1)*8 + rr8, bkb = (mid & 1)*16;

    {
        double s  = g_stats[((size_t)j*NI + i)*512 + tid*2];
        double s2 = g_stats[((size_t)j*NI + i)*512 + tid*2 + 1];
        double n  = (double)(NB*TOUT);
        float m   = (float)(s / n);
        float var = (float)(s2 / n) - m*m;
        float a   = bn_g[j*256 + tid] * rsqrtf(var + 1e-5f);
        aa[tid] = a;
        bb[tid] = bn_b[j*256 + tid] - a*m;
    }
    const float* Wsrc = c1_W + (size_t)j*128*256;
    for (int idx = tid; idx < 32768; idx += 256) {
        int o = idx >> 8, ch = idx & 255;
        u16 h, l; bsplit(Wsrc[idx], h, l);
        *(u16*)(smc + C1_WH + o*528 + ch*2) = h;
        *(u16*)(smc + C1_WL + o*528 + ch*2) = l;
    }
    float cb[2][2];
    #pragma unroll
    for (int ms = 0; ms < 2; ms++)
        #pragma unroll
        for (int hq = 0; hq < 2; hq++)
            cb[ms][hq] = c1_b[j*128 + warpM*32 + ms*16 + g + hq*8];

    float4 hreg[16];
    {
        const float4* h4 = (const float4*)(g_h + ((size_t)i*NB + bg*CBS)*16384);
        #pragma unroll
        for (int r = 0; r < 16; r++) hreg[r] = h4[tid + r*256];
    }

    for (int bs = 0; bs < CBS; bs++) {
        int b = bg*CBS + bs;
        size_t ib = (size_t)i*NB + b;
        __syncthreads();
        #pragma unroll
        for (int r = 0; r < 16; r++) {
            int idx4 = tid + r*256;
            int t = idx4 >> 6, c4 = (idx4 & 63) * 4;
            float4 hv = hreg[r];
            bool live = (t < TOUT);
            float v0 = live ? fmaxf(fmaf(aa[c4    ], hv.x, bb[c4    ]), 0.f) : 0.f;
            float v1 = live ? fmaxf(fmaf(aa[c4 + 1], hv.y, bb[c4 + 1]), 0.f) : 0.f;
            float v2 = live ? fmaxf(fmaf(aa[c4 + 2], hv.z, bb[c4 + 2]), 0.f) : 0.f;
            float v3 = live ? fmaxf(fmaf(aa[c4 + 3], hv.w, bb[c4 + 3]), 0.f) : 0.f;
            u16 h0,l0,h1,l1,h2,l2,h3,l3;
            bsplit(v0,h0,l0); bsplit(v1,h1,l1); bsplit(v2,h2,l2); bsplit(v3,h3,l3);
            *(u32*)(smc + C1_BH + t*528 + c4*2    ) = pk16(h0,h1);
            *(u32*)(smc + C1_BH + t*528 + c4*2 + 4) = pk16(h2,h3);
            *(u32*)(smc + C1_BL + t*528 + c4*2    ) = pk16(l0,l1);
            *(u32*)(smc + C1_BL + t*528 + c4*2 + 4) = pk16(l2,l3);
        }
        __syncthreads();
        if (bs + 1 < CBS) {
            const float4* h4 = (const float4*)(g_h + (ib + 1)*16384);
            #pragma unroll
            for (int r = 0; r < 16; r++) hreg[r] = h4[tid + r*256];
        }

        float C[2][4][4];
        #pragma unroll
        for (int ms = 0; ms < 2; ms++)
            #pragma unroll
            for (int ns = 0; ns < 4; ns++)
                #pragma unroll
                for (int q = 0; q < 4; q++) C[ms][ns][q] = 0.f;

        #pragma unroll
        for (int term = 0; term < 3; term++) {
            u32 aAddr = smb + ((term == 1) ? C1_WL : C1_WH)
                            + (u32)((warpM*32 + aro)*528 + akb);
            u32 bAddr = smb + ((term == 2) ? C1_BL : C1_BH)
                            + (u32)((warpN*32 + bro)*528 + bkb);
            #pragma unroll
            for (int kc = 0; kc < 16; kc++) {
                u32 A[2][4], B[4][2];
                ldsm_x4(A[0][0], A[0][1], A[0][2], A[0][3], aAddr + kc*32);
                ldsm_x4(A[1][0], A[1][1], A[1][2], A[1][3], aAddr + 16*528 + kc*32);
                ldsm_x4(B[0][0], B[0][1], B[1][0], B[1][1], bAddr + kc*32);
                ldsm_x4(B[2][0], B[2][1], B[3][0], B[3][1], bAddr + 16*528 + kc*32);
                #pragma unroll
                for (int ms = 0; ms < 2; ms++)
                    #pragma unroll
                    for (int ns = 0; ns < 4; ns++)
                        mma16816(C[ms][ns], A[ms], B[ns]);
            }
        }

        u16* xh = g_xh + ib*8192;
        u16* xl = g_xl + ib*8192;
        #pragma unroll
        for (int ms = 0; ms < 2; ms++) {
            int row0 = warpM*32 + ms*16 + g;
            #pragma unroll
            for (int ns = 0; ns < 4; ns++) {
                int tg = warpN*32 + ns*8 + t4*2;
                #pragma unroll
                for (int dt = 0; dt < 2; dt++) {
                    int t = tg + dt;
                    float vA = (t < TOUT) ? (C[ms][ns][dt]     + cb[ms][0]) : 0.f;
                    float vB = (t < TOUT) ? (C[ms][ns][dt + 2] + cb[ms][1]) : 0.f;
                    u16 h, l;
                    bsplit(vA, h, l);
                    xh[t*128 + row0]     = h; xl[t*128 + row0]     = l;
                    bsplit(vB, h, l);
                    xh[t*128 + row0 + 8] = h; xl[t*128 + row0 + 8] = l;
                }
            }
        }
    }
}

// ---------------- stage 6: W_fc GEMM via mma.sync + ldmatrix + max-over-t ----------
#define FC_WH 0
#define FC_WL 34816
#define FC_XH 69632
#define FC_XL 87040
#define FC_RED 104448
#define FC_SMEM_TOTAL 105472

__global__ __launch_bounds__(256, 2) void k_fc_mma(const float* __restrict__ W_fc,
                                                   const float* __restrict__ b_fc) {
    extern __shared__ char smc[];
    u32 smb = (u32)__cvta_generic_to_shared(smc);
    int lt = blockIdx.x, bg = blockIdx.y, i = blockIdx.z;
    int tid = threadIdx.x, wid = tid >> 5, lane = tid & 31;
    int g = lane >> 2, t4 = lane & 3;
    int warpM = wid >> 1, warpN = wid & 1;
    int mid = lane >> 3, rr8 = lane & 7;
    int aro = (mid & 1)*8 + rr8, akb = (mid >> 1)*16;
    int bro = (mid >> 1)*8 + rr8, bkb = (mid & 1)*16;

    const float* Wsrc = W_fc + (size_t)lt*128*128;
    for (int idx = tid; idx < 16384; idx += 256) {
        int m = idx >> 7, c = idx & 127;
        u16 h, l; bsplit(Wsrc[idx], h, l);
        *(u16*)(smc + FC_WH + m*272 + c*2) = h;
        *(u16*)(smc + FC_WL + m*272 + c*2) = l;
    }
    float bfc = (tid < 128) ? b_fc[lt*128 + tid] : 0.f;
    float* redbuf = (float*)(smc + FC_RED);   // [2][128]

    uint4 px[8];
    {
        size_t ib0 = (size_t)i*NB + bg*16;
        const uint4* sh = (const uint4*)(g_xh + ib0*8192);
        const uint4* sl = (const uint4*)(g_xl + ib0*8192);
        #pragma unroll
        for (int r = 0; r < 4; r++) { px[r] = sh[tid + r*256]; px[4 + r] = sl[tid + r*256]; }
    }

    for (int bs = 0; bs < 16; bs++) {
        size_t ib = (size_t)i*NB + bg*16 + bs;
        #pragma unroll
        for (int r = 0; r < 4; r++) {
            int u = tid + r*256;
            int t = u >> 4, sgm = u & 15;
            *(uint4*)(smc + FC_XH + t*272 + sgm*16) = px[r];
            *(uint4*)(smc + FC_XL + t*272 + sgm*16) = px[4 + r];
        }
        __syncthreads();
        if (bs + 1 < 16) {
            const uint4* sh = (const uint4*)(g_xh + (ib + 1)*8192);
            const uint4* sl = (const uint4*)(g_xl + (ib + 1)*8192);
            #pragma unroll
            for (int r = 0; r < 4; r++) { px[r] = sh[tid + r*256]; px[4 + r] = sl[tid + r*256]; }
        }

        float C[2][4][4];
        #pragma unroll
        for (int ms = 0; ms < 2; ms++)
            #pragma unroll
            for (int ns = 0; ns < 4; ns++)
                #pragma unroll
                for (int q = 0; q < 4; q++) C[ms][ns][q] = 0.f;

        #pragma unroll
        for (int term = 0; term < 3; term++) {
            u32 aAddr = smb + ((term == 1) ? FC_WL : FC_WH)
                            + (u32)((warpM*32 + aro)*272 + akb);
            u32 bAddr = smb + ((term == 2) ? FC_XL : FC_XH)
                            + (u32)((warpN*32 + bro)*272 + bkb);
            #pragma unroll
            for (int kc = 0; kc < 8; kc++) {
                u32 A[2][4], B[4][2];
                ldsm_x4(A[0][0], A[0][1], A[0][2], A[0][3], aAddr + kc*32);
                ldsm_x4(A[1][0], A[1][1], A[1][2], A[1][3], aAddr + 16*272 + kc*32);
                ldsm_x4(B[0][0], B[0][1], B[1][0], B[1][1], bAddr + kc*32);
                ldsm_x4(B[2][0], B[2][1], B[3][0], B[3][1], bAddr + 16*272 + kc*32);
                #pragma unroll
                for (int ms = 0; ms < 2; ms++)
                    #pragma unroll
                    for (int ns = 0; ns < 4; ns++)
                        mma16816(C[ms][ns], A[ms], B[ns]);
            }
        }

        #pragma unroll
        for (int ms = 0; ms < 2; ms++) {
            float mA = -1e30f, mB = -1e30f;
            #pragma unroll
            for (int ns = 0; ns < 4; ns++) {
                int tg = warpN*32 + ns*8 + t4*2;
                if (tg < 62)     { mA = fmaxf(mA, C[ms][ns][0]); mB = fmaxf(mB, C[ms][ns][2]); }
                if (tg + 1 < 62) { mA = fmaxf(mA, C[ms][ns][1]); mB = fmaxf(mB, C[ms][ns][3]); }
            }
            mA = fmaxf(mA, __shfl_xor_sync(0xffffffffu, mA, 1));
            mA = fmaxf(mA, __shfl_xor_sync(0xffffffffu, mA, 2));
            mB = fmaxf(mB, __shfl_xor_sync(0xffffffffu, mB, 1));
            mB = fmaxf(mB, __shfl_xor_sync(0xffffffffu, mB, 2));
            if (t4 == 0) {
                int row = warpM*32 + ms*16 + g;
                redbuf[warpN*128 + row]     = mA;
                redbuf[warpN*128 + row + 8] = mB;
            }
        }
        __syncthreads();
        if (tid < 128) {
            float y = fmaxf(redbuf[tid], redbuf[128 + tid]) + bfc;
            g_y[ib*1024 + lt*128 + tid] = y;
        }
    }
}

// ---------------- stage 7: normalize + dot ----------------
__global__ __launch_bounds__(256) void k_final(float* __restrict__ out) {
    __shared__ float r1[256], r2[256];
    int b = blockIdx.x, i = blockIdx.y, tid = threadIdx.x;
    const float* y = g_y + (size_t)(i*NB + b)*1024;
    const float* g = g_img_global + i*LL;
    float d = 0.f, ss = 0.f;
    for (int l = tid; l < 1024; l += 256) { float yv = y[l]; d = fmaf(yv, g[l], d); ss = fmaf(yv, yv, ss); }
    r1[tid] = d; r2[tid] = ss; __syncthreads();
    for (int s = 128; s > 0; s >>= 1) {
        if (tid < s) { r1[tid] += r1[tid+s]; r2[tid] += r2[tid+s]; }
        __syncthreads();
    }
    if (tid == 0) out[i*NB + b] = r1[0] / (sqrtf(r2[0]) * g_inorm[i]);
}

// ---------------- launch ----------------
extern "C" void kernel_launch(void* const* d_in, const int* in_sizes, int n_in,
                              void* d_out, int out_size) {
    (void)in_sizes; (void)n_in; (void)out_size;
    const float* img_embed = (const float*)d_in[0];
    const float* cap_embed = (const float*)d_in[1];
    const float* W_ri = (const float*)d_in[2];
    const float* b_ri = (const float*)d_in[3];
    const float* W_rt = (const float*)d_in[4];
    const float* b_rt = (const float*)d_in[5];
    const float* mk_W = (const float*)d_in[6];
    const float* mk_b = (const float*)d_in[7];
    // d_in[8]=mbias_W, d_in[9]=mbias_b, d_in[13]=ca_b: exactly cancelled by training-mode BN
    const float* wn_g = (const float*)d_in[10];
    const float* wn_b = (const float*)d_in[11];
    const float* ca_W = (const float*)d_in[12];
    const float* bn_g = (const float*)d_in[14];
    const float* bn_b = (const float*)d_in[15];
    const float* c1_W = (const float*)d_in[16];
    const float* c1_b = (const float*)d_in[17];
    const float* W_fc = (const float*)d_in[18];
    const float* b_fc = (const float*)d_in[19];
    float* out = (float*)d_out;

    const int CAP_SMEM = 300*64*4;
    const int GEN_SMEM = (128 + 8192)*4;
    cudaFuncSetAttribute((const void*)k_cap_red,      cudaFuncAttributeMaxDynamicSharedMemorySize, CAP_SMEM);
    cudaFuncSetAttribute((const void*)k_gen,          cudaFuncAttributeMaxDynamicSharedMemorySize, GEN_SMEM);
    cudaFuncSetAttribute((const void*)k_conv_mma<63>, cudaFuncAttributeMaxDynamicSharedMemorySize, CV_SMEM_TOTAL);
    cudaFuncSetAttribute((const void*)k_conv_mma<62>, cudaFuncAttributeMaxDynamicSharedMemorySize, CV_SMEM_TOTAL);
    cudaFuncSetAttribute((const void*)k_c1_mma<63>,   cudaFuncAttributeMaxDynamicSharedMemorySize, C1_SMEM_TOTAL);
    cudaFuncSetAttribute((const void*)k_c1_mma<62>,   cudaFuncAttributeMaxDynamicSharedMemorySize, C1_SMEM_TOTAL);
    cudaFuncSetAttribute((const void*)k_fc_mma,       cudaFuncAttributeMaxDynamicSharedMemorySize, FC_SMEM_TOTAL);

    k_img_prep<<<NI, 256>>>(img_embed, W_ri, b_ri);
    k_gen<<<NI*2*2, 256, GEN_SMEM>>>(mk_W, mk_b, wn_g, wn_b);
    k_cap_red<<<NB, 256, CAP_SMEM>>>(cap_embed, W_rt, b_rt, ca_W);

    // block j = 0 (T 64 -> 63)
    k_conv_mma<63><<<dim3(NB/CBS, NI, 2), 256, CV_SMEM_TOTAL>>>(0);
    k_c1_mma<63><<<dim3(NB/CBS, NI), 256, C1_SMEM_TOTAL>>>(bn_g, bn_b, c1_b, c1_W, 0);

    // block j = 1 (T 63 -> 62)
    k_conv_mma<62><<<dim3(NB/CBS, NI, 2), 256, CV_SMEM_TOTAL>>>(1);
    k_c1_mma<62><<<dim3(NB/CBS, NI), 256, C1_SMEM_TOTAL>>>(bn_g, bn_b, c1_b, c1_W, 1);

    // tensor-core W_fc + max (16 captions/CTA), then normalize + dot
    k_fc_mma<<<dim3(8, NB/16, NI), 256, FC_SMEM_TOTAL>>>(W_fc, b_fc);
    k_final<<<dim3(NB, NI), 256>>>(out);
}

// round 14
// speedup vs baseline: 1.0002x; 1.0002x over previous
#include <cuda_runtime.h>
#include <cuda_bf16.h>
#include <math.h>

#define NI 32     // images
#define NB 128    // captions
#define RR 128    // reduced channels
#define LL 1024   // latent
#define TT 64     // initial time

typedef unsigned long long u64;
typedef unsigned int u32;
typedef unsigned short u16;

// ---------------- warp mma.sync bf16 + ldmatrix (sm_75/80 baseline PTX) -------
__device__ __forceinline__ void mma16816(float c[4], const u32 a[4], const u32 b[2]) {
    asm volatile("mma.sync.aligned.m16n8k16.row.col.f32.bf16.bf16.f32 "
                 "{%0,%1,%2,%3}, {%4,%5,%6,%7}, {%8,%9}, {%0,%1,%2,%3};"
                 : "+f"(c[0]), "+f"(c[1]), "+f"(c[2]), "+f"(c[3])
                 : "r"(a[0]), "r"(a[1]), "r"(a[2]), "r"(a[3]), "r"(b[0]), "r"(b[1]));
}
__device__ __forceinline__ void ldsm_x4(u32& r0, u32& r1, u32& r2, u32& r3, u32 addr) {
    asm volatile("ldmatrix.sync.aligned.m8n8.x4.shared.b16 {%0,%1,%2,%3}, [%4];"
                 : "=r"(r0), "=r"(r1), "=r"(r2), "=r"(r3) : "r"(addr));
}
// truncation split: v = hh + hl + O(2^-16 v); v-hh exact (prefix subtraction)
__device__ __forceinline__ void fsplit(float v, u16& h, u16& l) {
    u32 uv = __float_as_uint(v);
    float r = v - __uint_as_float(uv & 0xffff0000u);
    h = (u16)(uv >> 16);
    l = (u16)(__float_as_uint(r) >> 16);
}
__device__ __forceinline__ u32 prmt7632(u32 a, u32 b) {
    u32 d; asm("prmt.b32 %0, %1, %2, 0x7632;" : "=r"(d) : "r"(a), "r"(b)); return d;
}
// paired split: hi = pack(trunc16(v0), trunc16(v1)), lo likewise for residuals
__device__ __forceinline__ void fsplit2(float v0, float v1, u32& hi, u32& lo) {
    u32 u0 = __float_as_uint(v0), u1 = __float_as_uint(v1);
    float r0 = v0 - __uint_as_float(u0 & 0xffff0000u);
    float r1 = v1 - __uint_as_float(u1 & 0xffff0000u);
    hi = prmt7632(u0, u1);
    lo = prmt7632(__float_as_uint(r0), __float_as_uint(r1));
}

// ---------------- device scratch (static globals; no allocation) ----------------
__device__ float  g_img_global[NI*LL];
__device__ float  g_inorm[NI];
__device__ float  g_img_vec[NI*RR];
__device__ float  g_kernT[NI*2*4*64*64];               // [(i2j)][g*2+k][o'][ci]
__device__ float  g_caT[2*4*64*64];                    // [j][g*2+k][row][ci]
__device__ double g_stats[2*NI*512];                   // per-j per-image per-channel sum/sumsq
__device__ float  g_h[(size_t)NI*NB*64*256];           // conv outputs, [ib][t][256ch]
__device__ __align__(16) u16 g_crh[NB*64*128];         // cap_red split hi, [b][t][c]
__device__ __align__(16) u16 g_crl[NB*64*128];
__device__ __align__(16) u16 g_xh[(size_t)NI*NB*64*128];  // x split hi, [ib][t][c]
__device__ __align__(16) u16 g_xl[(size_t)NI*NB*64*128];
__device__ float  g_y[(size_t)NI*NB*1024];             // max-pooled pre-norm

// ---------------- stage 1: image prep (mean, norm, hypernet base) ----------------
__global__ __launch_bounds__(256) void k_img_prep(const float* __restrict__ img_embed,
                                                  const float* __restrict__ W_ri,
                                                  const float* __restrict__ b_ri) {
    __shared__ float gsh[LL];
    __shared__ float red[256];
    int i = blockIdx.x, tid = threadIdx.x;
    float ssq = 0.f;
    for (int c = tid; c < LL; c += 256) {
        float s = 0.f;
        #pragma unroll
        for (int t = 0; t < 36; t++) s += img_embed[((size_t)i*36 + t)*LL + c];
        s *= (1.0f/36.0f);
        gsh[c] = s;
        g_img_global[i*LL + c] = s;
        ssq += s*s;
    }
    red[tid] = ssq; __syncthreads();
    for (int s = 128; s > 0; s >>= 1) { if (tid < s) red[tid] += red[tid+s]; __syncthreads(); }
    if (tid == 0) g_inorm[i] = sqrtf(red[0]);
    if (tid < RR) {
        int o = tid;
        float acc = b_ri[o];
        const float* w = W_ri + (size_t)o * LL;
        for (int c = 0; c < LL; c++) acc = fmaf(w[c], gsh[c], acc);
        g_img_vec[i*RR + o] = acc;
    }
}

// ---------------- stage 2: hypernet kernel gen + weight BN, 128 CTAs --------------
__global__ __launch_bounds__(256) void k_gen(const float* __restrict__ mk_W,
                                             const float* __restrict__ mk_b,
                                             const float* __restrict__ wn_g,
                                             const float* __restrict__ wn_b) {
    extern __shared__ float sm[];
    float* base = sm;          // 128
    float* kraw = sm + 128;    // 8192
    int bx = blockIdx.x, tid = threadIdx.x;
    int i = bx >> 2, j = (bx >> 1) & 1, half = bx & 1;
    {
        int z = bx*256 + tid;
        if (z < 2*NI*512) g_stats[z] = 0.0;
    }
    if (tid < RR) base[tid] = g_img_vec[i*RR + tid];
    __syncthreads();
    int fbase = half*8192;
    for (int f = tid; f < 8192; f += 256) {
        float acc = mk_b[j*16384 + fbase + f];
        const float* w = mk_W + ((size_t)j*16384 + fbase + f)*128;
        #pragma unroll 4
        for (int c = 0; c < 128; c++) acc = fmaf(w[c], base[c], acc);
        kraw[f] = acc;
    }
    __syncthreads();
    if (tid < 64) {
        int o = half*64 + tid;
        int g = o >> 6, op = o & 63;
        const float* kr = kraw + tid*128;
        float s = 0.f, s2 = 0.f;
        for (int c = 0; c < 128; c++) { float v = kr[c]; s += v; s2 += v*v; }
        float m   = s * (1.f/128.f);
        float var = s2 * (1.f/128.f) - m*m;
        float a   = wn_g[j*RR+o] * rsqrtf(var + 1e-5f);
        float bbv = wn_b[j*RR+o] - a*m;
        float* dst = g_kernT + (size_t)(i*2+j)*16384;
        for (int cik = 0; cik < 128; cik++) {
            int ci = cik >> 1, k = cik & 1;
            dst[((g*2+k)*64 + op)*64 + ci] = fmaf(a, kr[cik], bbv);
        }
    }
}

// ---------------- stage 3: caption reduction (split-bf16 out) + ca_W transform -----
__global__ __launch_bounds__(256) void k_cap_red(const float* __restrict__ cap_embed,
                                                 const float* __restrict__ W_rt,
                                                 const float* __restrict__ b_rt,
                                                 const float* __restrict__ ca_W) {
    extern __shared__ float sm[];
    float* ce = sm;                      // [c 300][t 64]
    int b = blockIdx.x, tid = threadIdx.x;
    for (int u = b*256 + tid; u < 32768; u += NB*256) {
        int ci = u & 63, row = (u >> 6) & 63, gk = (u >> 12) & 3, j2 = u >> 14;
        int o = (gk >> 1)*64 + row, k = gk & 1;
        g_caT[j2*16384 + (gk*64 + row)*64 + ci] = ca_W[((j2*128 + o)*64 + ci)*2 + k];
    }
    for (int idx = tid; idx < 300*TT; idx += 256) {
        int c = idx >> 6, t = idx & 63;
        ce[idx] = cap_embed[(size_t)b*TT*300 + t*300 + c];
    }
    __syncthreads();
    for (int q = tid; q < RR*16; q += 256) {
        int o = q >> 4, tq = (q & 15) * 4;
        float a0 = 0.f, a1 = 0.f, a2 = 0.f, a3 = 0.f;
        const float* w = W_rt + o*300;
        for (int c = 0; c < 300; c++) {
            float wv = w[c];
            float4 x4 = *(const float4*)(ce + c*TT + tq);
            a0 = fmaf(wv, x4.x, a0); a1 = fmaf(wv, x4.y, a1);
            a2 = fmaf(wv, x4.z, a2); a3 = fmaf(wv, x4.w, a3);
        }
        float bo = b_rt[o];
        float vv[4] = {a0 + bo, a1 + bo, a2 + bo, a3 + bo};
        #pragma unroll
        for (int n = 0; n < 4; n++) {
            u16 h, l; fsplit(vv[n], h, l);
            g_crh[b*8192 + (tq + n)*128 + o] = h;
            g_crl[b*8192 + (tq + n)*128 + o] = l;
        }
    }
}

// ---------------- stage 4: grouped convs via mma.sync + ldmatrix, g-split ----------
// B double-buffered: one barrier per caption, stores overlap previous MMA
#define CV_AH  0
#define CV_AL  36864
#define CV_B0H 73728
#define CV_B0L 83088
#define CV_B1H 92448
#define CV_B1L 101808
#define CV_SMEM_TOTAL 111168

template<int TOUT>
__global__ __launch_bounds__(256, 2) void k_conv_mma(int j) {
    extern __shared__ char smc[];
    u32 smb = (u32)__cvta_generic_to_shared(smc);
    int bg = blockIdx.x, i = blockIdx.y, g = blockIdx.z, tid = threadIdx.x;
    int wid = tid >> 5, lane = tid & 31, gq = lane >> 2, t4 = lane & 3;
    int warpM = wid >> 1, warpN = wid & 1;
    int mid = lane >> 3, rr8 = lane & 7;
    int aro = (mid & 1)*8 + rr8, akb = (mid >> 1)*16;
    int bro = (mid >> 1)*8 + rr8, bkb = (mid & 1)*16;

    const u32 bufH[2] = { (u32)CV_B0H, (u32)CV_B1H };
    const u32 bufL[2] = { (u32)CV_B0L, (u32)CV_B1L };

    // A build (truncation split)
    const float* kt = g_kernT + (size_t)(i*2 + j)*16384 + g*8192;
    const float* ct = g_caT + (size_t)j*16384 + g*8192;
    for (int idx = tid; idx < 16384; idx += 256) {
        int ci = idx & 63, row = (idx >> 6) & 127, k01 = idx >> 13;
        float v = (row < 64) ? kt[(k01*64 + row)*64 + ci]
                             : ct[(k01*64 + (row - 64))*64 + ci];
        u16 h, l; fsplit(v, h, l);
        int off = (k01*128 + row)*144 + ci*2;
        *(u16*)(smc + CV_AH + off) = h;
        *(u16*)(smc + CV_AL + off) = l;
    }
    // zero pad row 64 of both buffers once
    if (tid < 9) {
        *(uint4*)(smc + CV_B0H + 64*144 + tid*16) = make_uint4(0,0,0,0);
        *(uint4*)(smc + CV_B0L + 64*144 + tid*16) = make_uint4(0,0,0,0);
        *(uint4*)(smc + CV_B1H + 64*144 + tid*16) = make_uint4(0,0,0,0);
        *(uint4*)(smc + CV_B1L + 64*144 + tid*16) = make_uint4(0,0,0,0);
    }

    uint4 ph[2], pl[2];
    int b0 = bg*16;
    size_t ibase = (size_t)i*NB;
    {   // load bs=0 and store directly to buffer 0 (nothing reads yet)
        const uint4* sh = (const uint4*)((j == 0) ? (g_crh + (size_t)b0*8192) : (g_xh + (ibase + b0)*8192));
        const uint4* sl = (const uint4*)((j == 0) ? (g_crl + (size_t)b0*8192) : (g_xl + (ibase + b0)*8192));
        #pragma unroll
        for (int r = 0; r < 2; r++) {
            int u = tid + r*256;
            int t = u >> 3, s = u & 7;
            uint4 vh = sh[t*16 + g*8 + s];
            uint4 vl = sl[t*16 + g*8 + s];
            *(uint4*)(smc + CV_B0H + t*144 + s*16) = vh;
            *(uint4*)(smc + CV_B0L + t*144 + s*16) = vl;
        }
    }
    {   // prefetch bs=1
        int b1 = b0 + 1;
        const uint4* sh = (const uint4*)((j == 0) ? (g_crh + (size_t)b1*8192) : (g_xh + (ibase + b1)*8192));
        const uint4* sl = (const uint4*)((j == 0) ? (g_crl + (size_t)b1*8192) : (g_xl + (ibase + b1)*8192));
        #pragma unroll
        for (int r = 0; r < 2; r++) {
            int u = tid + r*256;
            int t = u >> 3, s = u & 7;
            ph[r] = sh[t*16 + g*8 + s];
            pl[r] = sl[t*16 + g*8 + s];
        }
    }

    float st_s[2][2], st_q[2][2];
    #pragma unroll
    for (int ms = 0; ms < 2; ms++)
        #pragma unroll
        for (int hq = 0; hq < 2; hq++) { st_s[ms][hq] = 0.f; st_q[ms][hq] = 0.f; }

    for (int bs = 0; bs < 16; bs++) {
        size_t ib = ibase + b0 + bs;
        int p = bs & 1;
        // single barrier: buf[p] stores visible; all warps done MMA(bs-1) on buf[p^1]
        __syncthreads();
        if (bs + 1 < 16) {
            int pn = p ^ 1;
            #pragma unroll
            for (int r = 0; r < 2; r++) {
                int u = tid + r*256;
                int t = u >> 3, s = u & 7;
                *(uint4*)(smc + bufH[pn] + t*144 + s*16) = ph[r];
                *(uint4*)(smc + bufL[pn] + t*144 + s*16) = pl[r];
            }
            if (bs + 2 < 16) {
                int b2 = b0 + bs + 2;
                const uint4* sh = (const uint4*)((j == 0) ? (g_crh + (size_t)b2*8192) : (g_xh + (ibase + b2)*8192));
                const uint4* sl = (const uint4*)((j == 0) ? (g_crl + (size_t)b2*8192) : (g_xl + (ibase + b2)*8192));
                #pragma unroll
                for (int r = 0; r < 2; r++) {
                    int u = tid + r*256;
                    int t = u >> 3, s = u & 7;
                    ph[r] = sh[t*16 + g*8 + s];
                    pl[r] = sl[t*16 + g*8 + s];
                }
            }
        }

        float C[2][4][4];
        #pragma unroll
        for (int ms = 0; ms < 2; ms++)
            #pragma unroll
            for (int ns = 0; ns < 4; ns++)
                #pragma unroll
                for (int q = 0; q < 4; q++) C[ms][ns][q] = 0.f;

        #pragma unroll
        for (int term = 0; term < 3; term++) {
            u32 Ab = smb + ((term == 1) ? CV_AL : CV_AH);
            u32 Bb = smb + ((term == 2) ? bufL[p] : bufH[p]);
            #pragma unroll
            for (int ks = 0; ks < 2; ks++) {
                u32 aAddr = Ab + (u32)((ks*128 + warpM*32 + aro)*144 + akb);
                u32 bAddr = Bb + (u32)((warpN*32 + ks + bro)*144 + bkb);
                #pragma unroll
                for (int kc = 0; kc < 4; kc++) {
                    u32 A[2][4], B[4][2];
                    ldsm_x4(A[0][0], A[0][1], A[0][2], A[0][3], aAddr + kc*32);
                    ldsm_x4(A[1][0], A[1][1], A[1][2], A[1][3], aAddr + 16*144 + kc*32);
                    ldsm_x4(B[0][0], B[0][1], B[1][0], B[1][1], bAddr + kc*32);
                    ldsm_x4(B[2][0], B[2][1], B[3][0], B[3][1], bAddr + 16*144 + kc*32);
                    #pragma unroll
                    for (int ms = 0; ms < 2; ms++)
                        #pragma unroll
                        for (int ns = 0; ns < 4; ns++)
                            mma16816(C[ms][ns], A[ms], B[ns]);
                }
            }
        }

        float* hp = g_h + ib*16384;
        #pragma unroll
        for (int ms = 0; ms < 2; ms++) {
            int r0 = warpM*32 + ms*16 + gq;
            int r1 = r0 + 8;
            int chA = (r0 < 64) ? (g*64 + r0) : (128 + g*64 + r0 - 64);
            int chB = (r1 < 64) ? (g*64 + r1) : (128 + g*64 + r1 - 64);
            #pragma unroll
            for (int ns = 0; ns < 4; ns++) {
                int tg = warpN*32 + ns*8 + t4*2;
                if (tg < TOUT) {
                    float v0 = C[ms][ns][0], v2 = C[ms][ns][2];
                    hp[tg*256 + chA] = v0;
                    hp[tg*256 + chB] = v2;
                    st_s[ms][0] += v0; st_q[ms][0] += v0*v0;
                    st_s[ms][1] += v2; st_q[ms][1] += v2*v2;
                }
                if (tg + 1 < TOUT) {
                    float v1 = C[ms][ns][1], v3 = C[ms][ns][3];
                    hp[(tg+1)*256 + chA] = v1;
                    hp[(tg+1)*256 + chB] = v3;
                    st_s[ms][0] += v1; st_q[ms][0] += v1*v1;
                    st_s[ms][1] += v3; st_q[ms][1] += v3*v3;
                }
            }
        }
    }
    double* st = g_stats + ((size_t)j*NI + i)*512;
    #pragma unroll
    for (int ms = 0; ms < 2; ms++)
        #pragma unroll
        for (int hq = 0; hq < 2; hq++) {
            float s = st_s[ms][hq], q = st_q[ms][hq];
            s += __shfl_xor_sync(0xffffffffu, s, 1);
            s += __shfl_xor_sync(0xffffffffu, s, 2);
            q += __shfl_xor_sync(0xffffffffu, q, 1);
            q += __shfl_xor_sync(0xffffffffu, q, 2);
            if (t4 == 0) {
                int r = warpM*32 + ms*16 + gq + hq*8;
                int ch = (r < 64) ? (g*64 + r) : (128 + g*64 + r - 64);
                atomicAdd(st + ch*2,     (double)s);
                atomicAdd(st + ch*2 + 1, (double)q);
            }
        }
}

// ---------------- stage 5: BN+ReLU + c1 via mma.sync + ldmatrix --------------------
#define C1_WH 0
#define C1_WL 67584
#define C1_BH 135168
#define C1_BL 168960
#define C1_AB 202752
#define C1_SMEM_TOTAL 204800

template<int TOUT>
__global__ __launch_bounds__(256) void k_c1_mma(const float* __restrict__ bn_g,
                                                const float* __restrict__ bn_b,
                                                const float* __restrict__ c1_b,
                                                const float* __restrict__ c1_W, int j) {
    extern __shared__ char smc[];
    u32 smb = (u32)__cvta_generic_to_shared(smc);
    float* aa = (float*)(smc + C1_AB);
    float* bb = aa + 256;
    int bg = blockIdx.x, i = blockIdx.y, tid = threadIdx.x;
    int wid = tid >> 5, lane = tid & 31, g = lane >> 2, t4 = lane & 3;
    int warpM = wid >> 1, warpN = wid & 1;
    int mid = lane >> 3, rr8 = lane & 7;
    int aro = (mid & 1)*8 + rr8, akb = (mid >> 1)*16;
    int bro = (mid >> 1)*8 + rr8, bkb = (mid & 1)*16;

    {
        double s  = g_stats[((size_t)j*NI + i)*512 + tid*2];
        double s2 = g_stats[((size_t)j*NI + i)*512 + tid*2 + 1];
        double n  = (double)(NB*TOUT);
        float m   = (float)(s / n);
        float var = (float)(s2 / n) - m*m;
        float a   = bn_g[j*256 + tid] * rsqrtf(var + 1e-5f);
        aa[tid] = a;
        bb[tid] = bn_b[j*256 + tid] - a*m;
    }
    const float* Wsrc = c1_W + (size_t)j*128*256;
    for (int idx = tid; idx < 32768; idx += 256) {
        int o = idx >> 8, ch = idx & 255;
        u16 h, l; fsplit(Wsrc[idx], h, l);
        *(u16*)(smc + C1_WH + o*528 + ch*2) = h;
        *(u16*)(smc + C1_WL + o*528 + ch*2) = l;
    }
    float cb[2][2];
    #pragma unroll
    for (int ms = 0; ms < 2; ms++)
        #pragma unroll
        for (int hq = 0; hq < 2; hq++)
            cb[ms][hq] = c1_b[j*128 + warpM*32 + ms*16 + g + hq*8];

    float4 hreg[16];
    {
        const float4* h4 = (const float4*)(g_h + ((size_t)i*NB + bg*16)*16384);
        #pragma unroll
        for (int r = 0; r < 16; r++) hreg[r] = h4[tid + r*256];
    }

    for (int bs = 0; bs < 16; bs++) {
        int b = bg*16 + bs;
        size_t ib = (size_t)i*NB + b;
        __syncthreads();
        #pragma unroll
        for (int r = 0; r < 16; r++) {
            int idx4 = tid + r*256;
            int t = idx4 >> 6, c4 = (idx4 & 63) * 4;
            float4 hv = hreg[r];
            bool live = (t < TOUT);
            float v0 = live ? fmaxf(fmaf(aa[c4    ], hv.x, bb[c4    ]), 0.f) : 0.f;
            float v1 = live ? fmaxf(fmaf(aa[c4 + 1], hv.y, bb[c4 + 1]), 0.f) : 0.f;
            float v2 = live ? fmaxf(fmaf(aa[c4 + 2], hv.z, bb[c4 + 2]), 0.f) : 0.f;
            float v3 = live ? fmaxf(fmaf(aa[c4 + 3], hv.w, bb[c4 + 3]), 0.f) : 0.f;
            u32 hA, lA, hB, lB;
            fsplit2(v0, v1, hA, lA);
            fsplit2(v2, v3, hB, lB);
            *(u32*)(smc + C1_BH + t*528 + c4*2    ) = hA;
            *(u32*)(smc + C1_BH + t*528 + c4*2 + 4) = hB;
            *(u32*)(smc + C1_BL + t*528 + c4*2    ) = lA;
            *(u32*)(smc + C1_BL + t*528 + c4*2 + 4) = lB;
        }
        __syncthreads();
        if (bs + 1 < 16) {
            const float4* h4 = (const float4*)(g_h + (ib + 1)*16384);
            #pragma unroll
            for (int r = 0; r < 16; r++) hreg[r] = h4[tid + r*256];
        }

        float C[2][4][4];
        #pragma unroll
        for (int ms = 0; ms < 2; ms++)
            #pragma unroll
            for (int ns = 0; ns < 4; ns++)
                #pragma unroll
                for (int q = 0; q < 4; q++) C[ms][ns][q] = 0.f;

        #pragma unroll
        for (int term = 0; term < 3; term++) {
            u32 aAddr = smb + ((term == 1) ? C1_WL : C1_WH)
                            + (u32)((warpM*32 + aro)*528 + akb);
            u32 bAddr = smb + ((term == 2) ? C1_BL : C1_BH)
                            + (u32)((warpN*32 + bro)*528 + bkb);
            #pragma unroll
            for (int kc = 0; kc < 16; kc++) {
                u32 A[2][4], B[4][2];
                ldsm_x4(A[0][0], A[0][1], A[0][2], A[0][3], aAddr + kc*32);
                ldsm_x4(A[1][0], A[1][1], A[1][2], A[1][3], aAddr + 16*528 + kc*32);
                ldsm_x4(B[0][0], B[0][1], B[1][0], B[1][1], bAddr + kc*32);
                ldsm_x4(B[2][0], B[2][1], B[3][0], B[3][1], bAddr + 16*528 + kc*32);
                #pragma unroll
                for (int ms = 0; ms < 2; ms++)
                    #pragma unroll
                    for (int ns = 0; ns < 4; ns++)
                        mma16816(C[ms][ns], A[ms], B[ns]);
            }
        }

        u16* xh = g_xh + ib*8192;
        u16* xl = g_xl + ib*8192;
        #pragma unroll
        for (int ms = 0; ms < 2; ms++) {
            int row0 = warpM*32 + ms*16 + g;
            #pragma unroll
            for (int ns = 0; ns < 4; ns++) {
                int tg = warpN*32 + ns*8 + t4*2;
                #pragma unroll
                for (int dt = 0; dt < 2; dt++) {
                    int t = tg + dt;
                    float vA = (t < TOUT) ? (C[ms][ns][dt]     + cb[ms][0]) : 0.f;
                    float vB = (t < TOUT) ? (C[ms][ns][dt + 2] + cb[ms][1]) : 0.f;
                    u16 h, l;
                    fsplit(vA, h, l);
                    xh[t*128 + row0]     = h; xl[t*128 + row0]     = l;
                    fsplit(vB, h, l);
                    xh[t*128 + row0 + 8] = h; xl[t*128 + row0 + 8] = l;
                }
            }
        }
    }
}

// ---------------- stage 6: W_fc GEMM via mma.sync + ldmatrix + max-over-t ----------
#define FC_WH 0
#define FC_WL 34816
#define FC_XH 69632
#define FC_XL 87040
#define FC_RED 104448
#define FC_SMEM_TOTAL 105472

__global__ __launch_bounds__(256, 2) void k_fc_mma(const float* __restrict__ W_fc,
                                                   const float* __restrict__ b_fc) {
    extern __shared__ char smc[];
    u32 smb = (u32)__cvta_generic_to_shared(smc);
    int lt = blockIdx.x, bg = blockIdx.y, i = blockIdx.z;
    int tid = threadIdx.x, wid = tid >> 5, lane = tid & 31;
    int g = lane >> 2, t4 = lane & 3;
    int warpM = wid >> 1, warpN = wid & 1;
    int mid = lane >> 3, rr8 = lane & 7;
    int aro = (mid & 1)*8 + rr8, akb = (mid >> 1)*16;
    int bro = (mid >> 1)*8 + rr8, bkb = (mid & 1)*16;

    const float* Wsrc = W_fc + (size_t)lt*128*128;
    for (int idx = tid; idx < 16384; idx += 256) {
        int m = idx >> 7, c = idx & 127;
        u16 h, l; fsplit(Wsrc[idx], h, l);
        *(u16*)(smc + FC_WH + m*272 + c*2) = h;
        *(u16*)(smc + FC_WL + m*272 + c*2) = l;
    }
    float bfc = (tid < 128) ? b_fc[lt*128 + tid] : 0.f;
    float* redbuf = (float*)(smc + FC_RED);   // [2][128]

    uint4 px[8];
    {
        size_t ib0 = (size_t)i*NB + bg*16;
        const uint4* sh = (const uint4*)(g_xh + ib0*8192);
        const uint4* sl = (const uint4*)(g_xl + ib0*8192);
        #pragma unroll
        for (int r = 0; r < 4; r++) { px[r] = sh[tid + r*256]; px[4 + r] = sl[tid + r*256]; }
    }

    for (int bs = 0; bs < 16; bs++) {
        size_t ib = (size_t)i*NB + bg*16 + bs;
        #pragma unroll
        for (int r = 0; r < 4; r++) {
            int u = tid + r*256;
            int t = u >> 4, sgm = u & 15;
            *(uint4*)(smc + FC_XH + t*272 + sgm*16) = px[r];
            *(uint4*)(smc + FC_XL + t*272 + sgm*16) = px[4 + r];
        }
        __syncthreads();
        if (bs + 1 < 16) {
            const uint4* sh = (const uint4*)(g_xh + (ib + 1)*8192);
            const uint4* sl = (const uint4*)(g_xl + (ib + 1)*8192);
            #pragma unroll
            for (int r = 0; r < 4; r++) { px[r] = sh[tid + r*256]; px[4 + r] = sl[tid + r*256]; }
        }

        float C[2][4][4];
        #pragma unroll
        for (int ms = 0; ms < 2; ms++)
            #pragma unroll
            for (int ns = 0; ns < 4; ns++)
                #pragma unroll
                for (int q = 0; q < 4; q++) C[ms][ns][q] = 0.f;

        #pragma unroll
        for (int term = 0; term < 3; term++) {
            u32 aAddr = smb + ((term == 1) ? FC_WL : FC_WH)
                            + (u32)((warpM*32 + aro)*272 + akb);
            u32 bAddr = smb + ((term == 2) ? FC_XL : FC_XH)
                            + (u32)((warpN*32 + bro)*272 + bkb);
            #pragma unroll
            for (int kc = 0; kc < 8; kc++) {
                u32 A[2][4], B[4][2];
                ldsm_x4(A[0][0], A[0][1], A[0][2], A[0][3], aAddr + kc*32);
                ldsm_x4(A[1][0], A[1][1], A[1][2], A[1][3], aAddr + 16*272 + kc*32);
                ldsm_x4(B[0][0], B[0][1], B[1][0], B[1][1], bAddr + kc*32);
                ldsm_x4(B[2][0], B[2][1], B[3][0], B[3][1], bAddr + 16*272 + kc*32);
                #pragma unroll
                for (int ms = 0; ms < 2; ms++)
                    #pragma unroll
                    for (int ns = 0; ns < 4; ns++)
                        mma16816(C[ms][ns], A[ms], B[ns]);
            }
        }

        #pragma unroll
        for (int ms = 0; ms < 2; ms++) {
            float mA = -1e30f, mB = -1e30f;
            #pragma unroll
            for (int ns = 0; ns < 4; ns++) {
                int tg = warpN*32 + ns*8 + t4*2;
                if (tg < 62)     { mA = fmaxf(mA, C[ms][ns][0]); mB = fmaxf(mB, C[ms][ns][2]); }
                if (tg + 1 < 62) { mA = fmaxf(mA, C[ms][ns][1]); mB = fmaxf(mB, C[ms][ns][3]); }
            }
            mA = fmaxf(mA, __shfl_xor_sync(0xffffffffu, mA, 1));
            mA = fmaxf(mA, __shfl_xor_sync(0xffffffffu, mA, 2));
            mB = fmaxf(mB, __shfl_xor_sync(0xffffffffu, mB, 1));
            mB = fmaxf(mB, __shfl_xor_sync(0xffffffffu, mB, 2));
            if (t4 == 0) {
                int row = warpM*32 + ms*16 + g;
                redbuf[warpN*128 + row]     = mA;
                redbuf[warpN*128 + row + 8] = mB;
            }
        }
        __syncthreads();
        if (tid < 128) {
            float y = fmaxf(redbuf[tid], redbuf[128 + tid]) + bfc;
            g_y[ib*1024 + lt*128 + tid] = y;
        }
    }
}

// ---------------- stage 7: normalize + dot ----------------
__global__ __launch_bounds__(256) void k_final(float* __restrict__ out) {
    __shared__ float r1[256], r2[256];
    int b = blockIdx.x, i = blockIdx.y, tid = threadIdx.x;
    const float* y = g_y + (size_t)(i*NB + b)*1024;
    const float* g = g_img_global + i*LL;
    float d = 0.f, ss = 0.f;
    for (int l = tid; l < 1024; l += 256) { float yv = y[l]; d = fmaf(yv, g[l], d); ss = fmaf(yv, yv, ss); }
    r1[tid] = d; r2[tid] = ss; __syncthreads();
    for (int s = 128; s > 0; s >>= 1) {
        if (tid < s) { r1[tid] += r1[tid+s]; r2[tid] += r2[tid+s]; }
        __syncthreads();
    }
    if (tid == 0) out[i*NB + b] = r1[0] / (sqrtf(r2[0]) * g_inorm[i]);
}

// ---------------- launch ----------------
extern "C" void kernel_launch(void* const* d_in, const int* in_sizes, int n_in,
                              void* d_out, int out_size) {
    (void)in_sizes; (void)n_in; (void)out_size;
    const float* img_embed = (const float*)d_in[0];
    const float* cap_embed = (const float*)d_in[1];
    const float* W_ri = (const float*)d_in[2];
    const float* b_ri = (const float*)d_in[3];
    const float* W_rt = (const float*)d_in[4];
    const float* b_rt = (const float*)d_in[5];
    const float* mk_W = (const float*)d_in[6];
    const float* mk_b = (const float*)d_in[7];
    // d_in[8]=mbias_W, d_in[9]=mbias_b, d_in[13]=ca_b: exactly cancelled by training-mode BN
    const float* wn_g = (const float*)d_in[10];
    const float* wn_b = (const float*)d_in[11];
    const float* ca_W = (const float*)d_in[12];
    const float* bn_g = (const float*)d_in[14];
    const float* bn_b = (const float*)d_in[15];
    const float* c1_W = (const float*)d_in[16];
    const float* c1_b = (const float*)d_in[17];
    const float* W_fc = (const float*)d_in[18];
    const float* b_fc = (const float*)d_in[19];
    float* out = (float*)d_out;

    const int CAP_SMEM = 300*64*4;
    const int GEN_SMEM = (128 + 8192)*4;
    cudaFuncSetAttribute((const void*)k_cap_red,      cudaFuncAttributeMaxDynamicSharedMemorySize, CAP_SMEM);
    cudaFuncSetAttribute((const void*)k_gen,          cudaFuncAttributeMaxDynamicSharedMemorySize, GEN_SMEM);
    cudaFuncSetAttribute((const void*)k_conv_mma<63>, cudaFuncAttributeMaxDynamicSharedMemorySize, CV_SMEM_TOTAL);
    cudaFuncSetAttribute((const void*)k_conv_mma<62>, cudaFuncAttributeMaxDynamicSharedMemorySize, CV_SMEM_TOTAL);
    cudaFuncSetAttribute((const void*)k_c1_mma<63>,   cudaFuncAttributeMaxDynamicSharedMemorySize, C1_SMEM_TOTAL);
    cudaFuncSetAttribute((const void*)k_c1_mma<62>,   cudaFuncAttributeMaxDynamicSharedMemorySize, C1_SMEM_TOTAL);
    cudaFuncSetAttribute((const void*)k_fc_mma,       cudaFuncAttributeMaxDynamicSharedMemorySize, FC_SMEM_TOTAL);

    k_img_prep<<<NI, 256>>>(img_embed, W_ri, b_ri);
    k_gen<<<NI*2*2, 256, GEN_SMEM>>>(mk_W, mk_b, wn_g, wn_b);
    k_cap_red<<<NB, 256, CAP_SMEM>>>(cap_embed, W_rt, b_rt, ca_W);

    // block j = 0 (T 64 -> 63)
    k_conv_mma<63><<<dim3(NB/16, NI, 2), 256, CV_SMEM_TOTAL>>>(0);
    k_c1_mma<63><<<dim3(NB/16, NI), 256, C1_SMEM_TOTAL>>>(bn_g, bn_b, c1_b, c1_W, 0);

    // block j = 1 (T 63 -> 62)
    k_conv_mma<62><<<dim3(NB/16, NI, 2), 256, CV_SMEM_TOTAL>>>(1);
    k_c1_mma<62><<<dim3(NB/16, NI), 256, C1_SMEM_TOTAL>>>(bn_g, bn_b, c1_b, c1_W, 1);

    // tensor-core W_fc + max (16 captions/CTA), then normalize + dot
    k_fc_mma<<<dim3(8, NB/16, NI), 256, FC_SMEM_TOTAL>>>(W_fc, b_fc);
    k_final<<<dim3(NB, NI), 256>>>(out);
}

// round 15
// speedup vs baseline: 1.0275x; 1.0273x over previous
#include <cuda_runtime.h>
#include <cuda_bf16.h>
#include <math.h>

#define NI 32     // images
#define NB 128    // captions
#define RR 128    // reduced channels
#define LL 1024   // latent
#define TT 64     // initial time

typedef unsigned long long u64;
typedef unsigned int u32;
typedef unsigned short u16;

// ---------------- warp mma.sync bf16 + ldmatrix (sm_75/80 baseline PTX) -------
__device__ __forceinline__ void mma16816(float c[4], const u32 a[4], const u32 b[2]) {
    asm volatile("mma.sync.aligned.m16n8k16.row.col.f32.bf16.bf16.f32 "
                 "{%0,%1,%2,%3}, {%4,%5,%6,%7}, {%8,%9}, {%0,%1,%2,%3};"
                 : "+f"(c[0]), "+f"(c[1]), "+f"(c[2]), "+f"(c[3])
                 : "r"(a[0]), "r"(a[1]), "r"(a[2]), "r"(a[3]), "r"(b[0]), "r"(b[1]));
}
__device__ __forceinline__ void ldsm_x4(u32& r0, u32& r1, u32& r2, u32& r3, u32 addr) {
    asm volatile("ldmatrix.sync.aligned.m8n8.x4.shared.b16 {%0,%1,%2,%3}, [%4];"
                 : "=r"(r0), "=r"(r1), "=r"(r2), "=r"(r3) : "r"(addr));
}
// truncation split: v = hh + hl + O(2^-16 v); v-hh exact (prefix subtraction)
__device__ __forceinline__ void fsplit(float v, u16& h, u16& l) {
    u32 uv = __float_as_uint(v);
    float r = v - __uint_as_float(uv & 0xffff0000u);
    h = (u16)(uv >> 16);
    l = (u16)(__float_as_uint(r) >> 16);
}
__device__ __forceinline__ u32 prmt7632(u32 a, u32 b) {
    u32 d; asm("prmt.b32 %0, %1, %2, 0x7632;" : "=r"(d) : "r"(a), "r"(b)); return d;
}
// paired split: hi = pack(trunc16(v0), trunc16(v1)), lo likewise for residuals
__device__ __forceinline__ void fsplit2(float v0, float v1, u32& hi, u32& lo) {
    u32 u0 = __float_as_uint(v0), u1 = __float_as_uint(v1);
    float r0 = v0 - __uint_as_float(u0 & 0xffff0000u);
    float r1 = v1 - __uint_as_float(u1 & 0xffff0000u);
    hi = prmt7632(u0, u1);
    lo = prmt7632(__float_as_uint(r0), __float_as_uint(r1));
}
__device__ __forceinline__ u64 pk64(u32 lo, u32 hi) {
    u64 v; asm("mov.b64 %0, {%1, %2};" : "=l"(v) : "r"(lo), "r"(hi)); return v;
}

// ---------------- device scratch (static globals; no allocation) ----------------
__device__ float  g_img_global[NI*LL];
__device__ float  g_inorm[NI];
__device__ float  g_img_vec[NI*RR];
__device__ float  g_kernT[NI*2*4*64*64];               // [(i2j)][g*2+k][o'][ci]
__device__ float  g_caT[2*4*64*64];                    // [j][g*2+k][row][ci]
__device__ double g_stats[2*NI*512];                   // per-j per-image per-channel sum/sumsq
__device__ float  g_h[(size_t)NI*NB*64*256];           // conv outputs, [ib][t][256ch]
__device__ __align__(16) u16 g_crh[NB*64*128];         // cap_red split hi, [b][t][c]
__device__ __align__(16) u16 g_crl[NB*64*128];
__device__ __align__(16) u16 g_xh[(size_t)NI*NB*64*128];  // x split hi, [ib][t][c]
__device__ __align__(16) u16 g_xl[(size_t)NI*NB*64*128];
__device__ float  g_y[(size_t)NI*NB*1024];             // max-pooled pre-norm

// ---------------- stage 1: image prep (mean, norm, hypernet base) ----------------
__global__ __launch_bounds__(256) void k_img_prep(const float* __restrict__ img_embed,
                                                  const float* __restrict__ W_ri,
                                                  const float* __restrict__ b_ri) {
    __shared__ float gsh[LL];
    __shared__ float red[256];
    int i = blockIdx.x, tid = threadIdx.x;
    float ssq = 0.f;
    for (int c = tid; c < LL; c += 256) {
        float s = 0.f;
        #pragma unroll
        for (int t = 0; t < 36; t++) s += img_embed[((size_t)i*36 + t)*LL + c];
        s *= (1.0f/36.0f);
        gsh[c] = s;
        g_img_global[i*LL + c] = s;
        ssq += s*s;
    }
    red[tid] = ssq; __syncthreads();
    for (int s = 128; s > 0; s >>= 1) { if (tid < s) red[tid] += red[tid+s]; __syncthreads(); }
    if (tid == 0) g_inorm[i] = sqrtf(red[0]);
    if (tid < RR) {
        int o = tid;
        float acc = b_ri[o];
        const float* w = W_ri + (size_t)o * LL;
        for (int c = 0; c < LL; c++) acc = fmaf(w[c], gsh[c], acc);
        g_img_vec[i*RR + o] = acc;
    }
}

// ---------------- stage 2: hypernet kernel gen + weight BN, 128 CTAs --------------
__global__ __launch_bounds__(256) void k_gen(const float* __restrict__ mk_W,
                                             const float* __restrict__ mk_b,
                                             const float* __restrict__ wn_g,
                                             const float* __restrict__ wn_b) {
    extern __shared__ float sm[];
    float* base = sm;          // 128
    float* kraw = sm + 128;    // 8192
    int bx = blockIdx.x, tid = threadIdx.x;
    int i = bx >> 2, j = (bx >> 1) & 1, half = bx & 1;
    {
        int z = bx*256 + tid;
        if (z < 2*NI*512) g_stats[z] = 0.0;
    }
    if (tid < RR) base[tid] = g_img_vec[i*RR + tid];
    __syncthreads();
    int fbase = half*8192;
    for (int f = tid; f < 8192; f += 256) {
        float acc = mk_b[j*16384 + fbase + f];
        const float* w = mk_W + ((size_t)j*16384 + fbase + f)*128;
        #pragma unroll 4
        for (int c = 0; c < 128; c++) acc = fmaf(w[c], base[c], acc);
        kraw[f] = acc;
    }
    __syncthreads();
    if (tid < 64) {
        int o = half*64 + tid;
        int g = o >> 6, op = o & 63;
        const float* kr = kraw + tid*128;
        float s = 0.f, s2 = 0.f;
        for (int c = 0; c < 128; c++) { float v = kr[c]; s += v; s2 += v*v; }
        float m   = s * (1.f/128.f);
        float var = s2 * (1.f/128.f) - m*m;
        float a   = wn_g[j*RR+o] * rsqrtf(var + 1e-5f);
        float bbv = wn_b[j*RR+o] - a*m;
        float* dst = g_kernT + (size_t)(i*2+j)*16384;
        for (int cik = 0; cik < 128; cik++) {
            int ci = cik >> 1, k = cik & 1;
            dst[((g*2+k)*64 + op)*64 + ci] = fmaf(a, kr[cik], bbv);
        }
    }
}

// ---------------- stage 3: caption reduction (split-bf16 out) + ca_W transform -----
__global__ __launch_bounds__(256) void k_cap_red(const float* __restrict__ cap_embed,
                                                 const float* __restrict__ W_rt,
                                                 const float* __restrict__ b_rt,
                                                 const float* __restrict__ ca_W) {
    extern __shared__ float sm[];
    float* ce = sm;                      // [c 300][t 64]
    int b = blockIdx.x, tid = threadIdx.x;
    for (int u = b*256 + tid; u < 32768; u += NB*256) {
        int ci = u & 63, row = (u >> 6) & 63, gk = (u >> 12) & 3, j2 = u >> 14;
        int o = (gk >> 1)*64 + row, k = gk & 1;
        g_caT[j2*16384 + (gk*64 + row)*64 + ci] = ca_W[((j2*128 + o)*64 + ci)*2 + k];
    }
    for (int idx = tid; idx < 300*TT; idx += 256) {
        int c = idx >> 6, t = idx & 63;
        ce[idx] = cap_embed[(size_t)b*TT*300 + t*300 + c];
    }
    __syncthreads();
    for (int q = tid; q < RR*16; q += 256) {
        int o = q >> 4, tq = (q & 15) * 4;
        float a0 = 0.f, a1 = 0.f, a2 = 0.f, a3 = 0.f;
        const float* w = W_rt + o*300;
        for (int c = 0; c < 300; c++) {
            float wv = w[c];
            float4 x4 = *(const float4*)(ce + c*TT + tq);
            a0 = fmaf(wv, x4.x, a0); a1 = fmaf(wv, x4.y, a1);
            a2 = fmaf(wv, x4.z, a2); a3 = fmaf(wv, x4.w, a3);
        }
        float bo = b_rt[o];
        float vv[4] = {a0 + bo, a1 + bo, a2 + bo, a3 + bo};
        #pragma unroll
        for (int n = 0; n < 4; n++) {
            u16 h, l; fsplit(vv[n], h, l);
            g_crh[b*8192 + (tq + n)*128 + o] = h;
            g_crl[b*8192 + (tq + n)*128 + o] = l;
        }
    }
}

// ---------------- stage 4: grouped convs via mma.sync + ldmatrix, g-split ----------
// single B buffer (R12-validated), pad-zero hoisted, register prefetch
#define CV_AH 0
#define CV_AL 36864
#define CV_BH 73728
#define CV_BL 83088
#define CV_SMEM_TOTAL 92448

template<int TOUT>
__global__ __launch_bounds__(256, 2) void k_conv_mma(int j) {
    extern __shared__ char smc[];
    u32 smb = (u32)__cvta_generic_to_shared(smc);
    int bg = blockIdx.x, i = blockIdx.y, g = blockIdx.z, tid = threadIdx.x;
    int wid = tid >> 5, lane = tid & 31, gq = lane >> 2, t4 = lane & 3;
    int warpM = wid >> 1, warpN = wid & 1;
    int mid = lane >> 3, rr8 = lane & 7;
    int aro = (mid & 1)*8 + rr8, akb = (mid >> 1)*16;
    int bro = (mid >> 1)*8 + rr8, bkb = (mid & 1)*16;

    const float* kt = g_kernT + (size_t)(i*2 + j)*16384 + g*8192;
    const float* ct = g_caT + (size_t)j*16384 + g*8192;
    for (int idx = tid; idx < 16384; idx += 256) {
        int ci = idx & 63, row = (idx >> 6) & 127, k01 = idx >> 13;
        float v = (row < 64) ? kt[(k01*64 + row)*64 + ci]
                             : ct[(k01*64 + (row - 64))*64 + ci];
        u16 h, l; fsplit(v, h, l);
        int off = (k01*128 + row)*144 + ci*2;
        *(u16*)(smc + CV_AH + off) = h;
        *(u16*)(smc + CV_AL + off) = l;
    }
    if (tid < 9) {
        *(uint4*)(smc + CV_BH + 64*144 + tid*16) = make_uint4(0,0,0,0);
        *(uint4*)(smc + CV_BL + 64*144 + tid*16) = make_uint4(0,0,0,0);
    }

    uint4 ph[2], pl[2];
    {
        int b0 = bg*16;
        size_t ib0 = (size_t)i*NB + b0;
        const uint4* sh = (const uint4*)((j == 0) ? (g_crh + (size_t)b0*8192) : (g_xh + ib0*8192));
        const uint4* sl = (const uint4*)((j == 0) ? (g_crl + (size_t)b0*8192) : (g_xl + ib0*8192));
        #pragma unroll
        for (int r = 0; r < 2; r++) {
            int u = tid + r*256;
            int t = u >> 3, s = u & 7;
            ph[r] = sh[t*16 + g*8 + s];
            pl[r] = sl[t*16 + g*8 + s];
        }
    }

    float st_s[2][2], st_q[2][2];
    #pragma unroll
    for (int ms = 0; ms < 2; ms++)
        #pragma unroll
        for (int hq = 0; hq < 2; hq++) { st_s[ms][hq] = 0.f; st_q[ms][hq] = 0.f; }

    for (int bs = 0; bs < 16; bs++) {
        size_t ib = (size_t)i*NB + bg*16 + bs;
        __syncthreads();
        #pragma unroll
        for (int r = 0; r < 2; r++) {
            int u = tid + r*256;
            int t = u >> 3, s = u & 7;
            *(uint4*)(smc + CV_BH + t*144 + s*16) = ph[r];
            *(uint4*)(smc + CV_BL + t*144 + s*16) = pl[r];
        }
        __syncthreads();
        if (bs + 1 < 16) {
            int b2 = bg*16 + bs + 1;
            size_t ib2 = (size_t)i*NB + b2;
            const uint4* sh = (const uint4*)((j == 0) ? (g_crh + (size_t)b2*8192) : (g_xh + ib2*8192));
            const uint4* sl = (const uint4*)((j == 0) ? (g_crl + (size_t)b2*8192) : (g_xl + ib2*8192));
            #pragma unroll
            for (int r = 0; r < 2; r++) {
                int u = tid + r*256;
                int t = u >> 3, s = u & 7;
                ph[r] = sh[t*16 + g*8 + s];
                pl[r] = sl[t*16 + g*8 + s];
            }
        }

        float C[2][4][4];
        #pragma unroll
        for (int ms = 0; ms < 2; ms++)
            #pragma unroll
            for (int ns = 0; ns < 4; ns++)
                #pragma unroll
                for (int q = 0; q < 4; q++) C[ms][ns][q] = 0.f;

        #pragma unroll
        for (int term = 0; term < 3; term++) {
            u32 Ab = smb + ((term == 1) ? CV_AL : CV_AH);
            u32 Bb = smb + ((term == 2) ? CV_BL : CV_BH);
            #pragma unroll
            for (int ks = 0; ks < 2; ks++) {
                u32 aAddr = Ab + (u32)((ks*128 + warpM*32 + aro)*144 + akb);
                u32 bAddr = Bb + (u32)((warpN*32 + ks + bro)*144 + bkb);
                #pragma unroll
                for (int kc = 0; kc < 4; kc++) {
                    u32 A[2][4], B[4][2];
                    ldsm_x4(A[0][0], A[0][1], A[0][2], A[0][3], aAddr + kc*32);
                    ldsm_x4(A[1][0], A[1][1], A[1][2], A[1][3], aAddr + 16*144 + kc*32);
                    ldsm_x4(B[0][0], B[0][1], B[1][0], B[1][1], bAddr + kc*32);
                    ldsm_x4(B[2][0], B[2][1], B[3][0], B[3][1], bAddr + 16*144 + kc*32);
                    #pragma unroll
                    for (int ms = 0; ms < 2; ms++)
                        #pragma unroll
                        for (int ns = 0; ns < 4; ns++)
                            mma16816(C[ms][ns], A[ms], B[ns]);
                }
            }
        }

        float* hp = g_h + ib*16384;
        #pragma unroll
        for (int ms = 0; ms < 2; ms++) {
            int r0 = warpM*32 + ms*16 + gq;
            int r1 = r0 + 8;
            int chA = (r0 < 64) ? (g*64 + r0) : (128 + g*64 + r0 - 64);
            int chB = (r1 < 64) ? (g*64 + r1) : (128 + g*64 + r1 - 64);
            #pragma unroll
            for (int ns = 0; ns < 4; ns++) {
                int tg = warpN*32 + ns*8 + t4*2;
                if (tg < TOUT) {
                    float v0 = C[ms][ns][0], v2 = C[ms][ns][2];
                    hp[tg*256 + chA] = v0;
                    hp[tg*256 + chB] = v2;
                    st_s[ms][0] += v0; st_q[ms][0] += v0*v0;
                    st_s[ms][1] += v2; st_q[ms][1] += v2*v2;
                }
                if (tg + 1 < TOUT) {
                    float v1 = C[ms][ns][1], v3 = C[ms][ns][3];
                    hp[(tg+1)*256 + chA] = v1;
                    hp[(tg+1)*256 + chB] = v3;
                    st_s[ms][0] += v1; st_q[ms][0] += v1*v1;
                    st_s[ms][1] += v3; st_q[ms][1] += v3*v3;
                }
            }
        }
    }
    double* st = g_stats + ((size_t)j*NI + i)*512;
    #pragma unroll
    for (int ms = 0; ms < 2; ms++)
        #pragma unroll
        for (int hq = 0; hq < 2; hq++) {
            float s = st_s[ms][hq], q = st_q[ms][hq];
            s += __shfl_xor_sync(0xffffffffu, s, 1);
            s += __shfl_xor_sync(0xffffffffu, s, 2);
            q += __shfl_xor_sync(0xffffffffu, q, 1);
            q += __shfl_xor_sync(0xffffffffu, q, 2);
            if (t4 == 0) {
                int r = warpM*32 + ms*16 + gq + hq*8;
                int ch = (r < 64) ? (g*64 + r) : (128 + g*64 + r - 64);
                atomicAdd(st + ch*2,     (double)s);
                atomicAdd(st + ch*2 + 1, (double)q);
            }
        }
}

// ---------------- stage 5: BN+ReLU + c1 via mma.sync + ldmatrix --------------------
#define C1_WH 0
#define C1_WL 67584
#define C1_BH 135168
#define C1_BL 168960
#define C1_AB 202752
#define C1_SMEM_TOTAL 204800

template<int TOUT>
__global__ __launch_bounds__(256) void k_c1_mma(const float* __restrict__ bn_g,
                                                const float* __restrict__ bn_b,
                                                const float* __restrict__ c1_b,
                                                const float* __restrict__ c1_W, int j) {
    extern __shared__ char smc[];
    u32 smb = (u32)__cvta_generic_to_shared(smc);
    float* aa = (float*)(smc + C1_AB);
    float* bb = aa + 256;
    int bg = blockIdx.x, i = blockIdx.y, tid = threadIdx.x;
    int wid = tid >> 5, lane = tid & 31, g = lane >> 2, t4 = lane & 3;
    int warpM = wid >> 1, warpN = wid & 1;
    int mid = lane >> 3, rr8 = lane & 7;
    int aro = (mid & 1)*8 + rr8, akb = (mid >> 1)*16;
    int bro = (mid >> 1)*8 + rr8, bkb = (mid & 1)*16;

    {
        double s  = g_stats[((size_t)j*NI + i)*512 + tid*2];
        double s2 = g_stats[((size_t)j*NI + i)*512 + tid*2 + 1];
        double n  = (double)(NB*TOUT);
        float m   = (float)(s / n);
        float var = (float)(s2 / n) - m*m;
        float a   = bn_g[j*256 + tid] * rsqrtf(var + 1e-5f);
        aa[tid] = a;
        bb[tid] = bn_b[j*256 + tid] - a*m;
    }
    const float* Wsrc = c1_W + (size_t)j*128*256;
    for (int idx = tid; idx < 32768; idx += 256) {
        int o = idx >> 8, ch = idx & 255;
        u16 h, l; fsplit(Wsrc[idx], h, l);
        *(u16*)(smc + C1_WH + o*528 + ch*2) = h;
        *(u16*)(smc + C1_WL + o*528 + ch*2) = l;
    }
    float cb[2][2];
    #pragma unroll
    for (int ms = 0; ms < 2; ms++)
        #pragma unroll
        for (int hq = 0; hq < 2; hq++)
            cb[ms][hq] = c1_b[j*128 + warpM*32 + ms*16 + g + hq*8];

    float4 hreg[16];
    {
        const float4* h4 = (const float4*)(g_h + ((size_t)i*NB + bg*16)*16384);
        #pragma unroll
        for (int r = 0; r < 16; r++) hreg[r] = h4[tid + r*256];
    }

    for (int bs = 0; bs < 16; bs++) {
        int b = bg*16 + bs;
        size_t ib = (size_t)i*NB + b;
        __syncthreads();
        #pragma unroll
        for (int r = 0; r < 16; r++) {
            int idx4 = tid + r*256;
            int t = idx4 >> 6, c4 = (idx4 & 63) * 4;
            float4 hv = hreg[r];
            bool live = (t < TOUT);
            float v0 = live ? fmaxf(fmaf(aa[c4    ], hv.x, bb[c4    ]), 0.f) : 0.f;
            float v1 = live ? fmaxf(fmaf(aa[c4 + 1], hv.y, bb[c4 + 1]), 0.f) : 0.f;
            float v2 = live ? fmaxf(fmaf(aa[c4 + 2], hv.z, bb[c4 + 2]), 0.f) : 0.f;
            float v3 = live ? fmaxf(fmaf(aa[c4 + 3], hv.w, bb[c4 + 3]), 0.f) : 0.f;
            u32 hA, lA, hB, lB;
            fsplit2(v0, v1, hA, lA);
            fsplit2(v2, v3, hB, lB);
            *(u64*)(smc + C1_BH + t*528 + c4*2) = pk64(hA, hB);
            *(u64*)(smc + C1_BL + t*528 + c4*2) = pk64(lA, lB);
        }
        __syncthreads();
        if (bs + 1 < 16) {
            const float4* h4 = (const float4*)(g_h + (ib + 1)*16384);
            #pragma unroll
            for (int r = 0; r < 16; r++) hreg[r] = h4[tid + r*256];
        }

        float C[2][4][4];
        #pragma unroll
        for (int ms = 0; ms < 2; ms++)
            #pragma unroll
            for (int ns = 0; ns < 4; ns++)
                #pragma unroll
                for (int q = 0; q < 4; q++) C[ms][ns][q] = 0.f;

        #pragma unroll
        for (int term = 0; term < 3; term++) {
            u32 aAddr = smb + ((term == 1) ? C1_WL : C1_WH)
                            + (u32)((warpM*32 + aro)*528 + akb);
            u32 bAddr = smb + ((term == 2) ? C1_BL : C1_BH)
                            + (u32)((warpN*32 + bro)*528 + bkb);
            #pragma unroll
            for (int kc = 0; kc < 16; kc++) {
                u32 A[2][4], B[4][2];
                ldsm_x4(A[0][0], A[0][1], A[0][2], A[0][3], aAddr + kc*32);
                ldsm_x4(A[1][0], A[1][1], A[1][2], A[1][3], aAddr + 16*528 + kc*32);
                ldsm_x4(B[0][0], B[0][1], B[1][0], B[1][1], bAddr + kc*32);
                ldsm_x4(B[2][0], B[2][1], B[3][0], B[3][1], bAddr + 16*528 + kc*32);
                #pragma unroll
                for (int ms = 0; ms < 2; ms++)
                    #pragma unroll
                    for (int ns = 0; ns < 4; ns++)
                        mma16816(C[ms][ns], A[ms], B[ns]);
            }
        }

        u16* xh = g_xh + ib*8192;
        u16* xl = g_xl + ib*8192;
        #pragma unroll
        for (int ms = 0; ms < 2; ms++) {
            int row0 = warpM*32 + ms*16 + g;
            #pragma unroll
            for (int ns = 0; ns < 4; ns++) {
                int tg = warpN*32 + ns*8 + t4*2;
                #pragma unroll
                for (int dt = 0; dt < 2; dt++) {
                    int t = tg + dt;
                    float vA = (t < TOUT) ? (C[ms][ns][dt]     + cb[ms][0]) : 0.f;
                    float vB = (t < TOUT) ? (C[ms][ns][dt + 2] + cb[ms][1]) : 0.f;
                    u16 h, l;
                    fsplit(vA, h, l);
                    xh[t*128 + row0]     = h; xl[t*128 + row0]     = l;
                    fsplit(vB, h, l);
                    xh[t*128 + row0 + 8] = h; xl[t*128 + row0 + 8] = l;
                }
            }
        }
    }
}

// ---------------- stage 6: W_fc GEMM via mma.sync + ldmatrix + max-over-t ----------
// sync-elided loop: trailing redbuf barrier doubles as next iteration's B-protect
#define FC_WH 0
#define FC_WL 34816
#define FC_XH 69632
#define FC_XL 87040
#define FC_RED 104448
#define FC_SMEM_TOTAL 105472

__global__ __launch_bounds__(256, 2) void k_fc_mma(const float* __restrict__ W_fc,
                                                   const float* __restrict__ b_fc) {
    extern __shared__ char smc[];
    u32 smb = (u32)__cvta_generic_to_shared(smc);
    int lt = blockIdx.x, bg = blockIdx.y, i = blockIdx.z;
    int tid = threadIdx.x, wid = tid >> 5, lane = tid & 31;
    int g = lane >> 2, t4 = lane & 3;
    int warpM = wid >> 1, warpN = wid & 1;
    int mid = lane >> 3, rr8 = lane & 7;
    int aro = (mid & 1)*8 + rr8, akb = (mid >> 1)*16;
    int bro = (mid >> 1)*8 + rr8, bkb = (mid & 1)*16;

    const float* Wsrc = W_fc + (size_t)lt*128*128;
    for (int idx = tid; idx < 16384; idx += 256) {
        int m = idx >> 7, c = idx & 127;
        u16 h, l; fsplit(Wsrc[idx], h, l);
        *(u16*)(smc + FC_WH + m*272 + c*2) = h;
        *(u16*)(smc + FC_WL + m*272 + c*2) = l;
    }
    float bfc = (tid < 128) ? b_fc[lt*128 + tid] : 0.f;
    float* redbuf = (float*)(smc + FC_RED);   // [2][128]

    uint4 px[8];
    {
        size_t ib0 = (size_t)i*NB + bg*16;
        const uint4* sh = (const uint4*)(g_xh + ib0*8192);
        const uint4* sl = (const uint4*)(g_xl + ib0*8192);
        #pragma unroll
        for (int r = 0; r < 4; r++) { px[r] = sh[tid + r*256]; px[4 + r] = sl[tid + r*256]; }
    }

    for (int bs = 0; bs < 16; bs++) {
        size_t ib = (size_t)i*NB + bg*16 + bs;
        #pragma unroll
        for (int r = 0; r < 4; r++) {
            int u = tid + r*256;
            int t = u >> 4, sgm = u & 15;
            *(uint4*)(smc + FC_XH + t*272 + sgm*16) = px[r];
            *(uint4*)(smc + FC_XL + t*272 + sgm*16) = px[4 + r];
        }
        __syncthreads();   // B (and W on iter 0) visible to all warps
        if (bs + 1 < 16) {
            const uint4* sh = (const uint4*)(g_xh + (ib + 1)*8192);
            const uint4* sl = (const uint4*)(g_xl + (ib + 1)*8192);
            #pragma unroll
            for (int r = 0; r < 4; r++) { px[r] = sh[tid + r*256]; px[4 + r] = sl[tid + r*256]; }
        }

        float C[2][4][4];
        #pragma unroll
        for (int ms = 0; ms < 2; ms++)
            #pragma unroll
            for (int ns = 0; ns < 4; ns++)
                #pragma unroll
                for (int q = 0; q < 4; q++) C[ms][ns][q] = 0.f;

        #pragma unroll
        for (int term = 0; term < 3; term++) {
            u32 aAddr = smb + ((term == 1) ? FC_WL : FC_WH)
                            + (u32)((warpM*32 + aro)*272 + akb);
            u32 bAddr = smb + ((term == 2) ? FC_XL : FC_XH)
                            + (u32)((warpN*32 + bro)*272 + bkb);
            #pragma unroll
            for (int kc = 0; kc < 8; kc++) {
                u32 A[2][4], B[4][2];
                ldsm_x4(A[0][0], A[0][1], A[0][2], A[0][3], aAddr + kc*32);
                ldsm_x4(A[1][0], A[1][1], A[1][2], A[1][3], aAddr + 16*272 + kc*32);
                ldsm_x4(B[0][0], B[0][1], B[1][0], B[1][1], bAddr + kc*32);
                ldsm_x4(B[2][0], B[2][1], B[3][0], B[3][1], bAddr + 16*272 + kc*32);
                #pragma unroll
                for (int ms = 0; ms < 2; ms++)
                    #pragma unroll
                    for (int ns = 0; ns < 4; ns++)
                        mma16816(C[ms][ns], A[ms], B[ns]);
            }
        }

        #pragma unroll
        for (int ms = 0; ms < 2; ms++) {
            float mA = -1e30f, mB = -1e30f;
            #pragma unroll
            for (int ns = 0; ns < 4; ns++) {
                int tg = warpN*32 + ns*8 + t4*2;
                if (tg < 62)     { mA = fmaxf(mA, C[ms][ns][0]); mB = fmaxf(mB, C[ms][ns][2]); }
                if (tg + 1 < 62) { mA = fmaxf(mA, C[ms][ns][1]); mB = fmaxf(mB, C[ms][ns][3]); }
            }
            mA = fmaxf(mA, __shfl_xor_sync(0xffffffffu, mA, 1));
            mA = fmaxf(mA, __shfl_xor_sync(0xffffffffu, mA, 2));
            mB = fmaxf(mB, __shfl_xor_sync(0xffffffffu, mB, 1));
            mB = fmaxf(mB, __shfl_xor_sync(0xffffffffu, mB, 2));
            if (t4 == 0) {
                int row = warpM*32 + ms*16 + g;
                redbuf[warpN*128 + row]     = mA;
                redbuf[warpN*128 + row + 8] = mB;
            }
        }
        __syncthreads();   // redbuf ready; also orders MMA reads before next B store
        if (tid < 128) {
            float y = fmaxf(redbuf[tid], redbuf[128 + tid]) + bfc;
            g_y[ib*1024 + lt*128 + tid] = y;
        }
    }
}

// ---------------- stage 7: normalize + dot ----------------
__global__ __launch_bounds__(256) void k_final(float* __restrict__ out) {
    __shared__ float r1[256], r2[256];
    int b = blockIdx.x, i = blockIdx.y, tid = threadIdx.x;
    const float* y = g_y + (size_t)(i*NB + b)*1024;
    const float* g = g_img_global + i*LL;
    float d = 0.f, ss = 0.f;
    for (int l = tid; l < 1024; l += 256) { float yv = y[l]; d = fmaf(yv, g[l], d); ss = fmaf(yv, yv, ss); }
    r1[tid] = d; r2[tid] = ss; __syncthreads();
    for (int s = 128; s > 0; s >>= 1) {
        if (tid < s) { r1[tid] += r1[tid+s]; r2[tid] += r2[tid+s]; }
        __syncthreads();
    }
    if (tid == 0) out[i*NB + b] = r1[0] / (sqrtf(r2[0]) * g_inorm[i]);
}

// ---------------- launch ----------------
extern "C" void kernel_launch(void* const* d_in, const int* in_sizes, int n_in,
                              void* d_out, int out_size) {
    (void)in_sizes; (void)n_in; (void)out_size;
    const float* img_embed = (const float*)d_in[0];
    const float* cap_embed = (const float*)d_in[1];
    const float* W_ri = (const float*)d_in[2];
    const float* b_ri = (const float*)d_in[3];
    const float* W_rt = (const float*)d_in[4];
    const float* b_rt = (const float*)d_in[5];
    const float* mk_W = (const float*)d_in[6];
    const float* mk_b = (const float*)d_in[7];
    // d_in[8]=mbias_W, d_in[9]=mbias_b, d_in[13]=ca_b: exactly cancelled by training-mode BN
    const float* wn_g = (const float*)d_in[10];
    const float* wn_b = (const float*)d_in[11];
    const float* ca_W = (const float*)d_in[12];
    const float* bn_g = (const float*)d_in[14];
    const float* bn_b = (const float*)d_in[15];
    const float* c1_W = (const float*)d_in[16];
    const float* c1_b = (const float*)d_in[17];
    const float* W_fc = (const float*)d_in[18];
    const float* b_fc = (const float*)d_in[19];
    float* out = (float*)d_out;

    const int CAP_SMEM = 300*64*4;
    const int GEN_SMEM = (128 + 8192)*4;
    cudaFuncSetAttribute((const void*)k_cap_red,      cudaFuncAttributeMaxDynamicSharedMemorySize, CAP_SMEM);
    cudaFuncSetAttribute((const void*)k_gen,          cudaFuncAttributeMaxDynamicSharedMemorySize, GEN_SMEM);
    cudaFuncSetAttribute((const void*)k_conv_mma<63>, cudaFuncAttributeMaxDynamicSharedMemorySize, CV_SMEM_TOTAL);
    cudaFuncSetAttribute((const void*)k_conv_mma<62>, cudaFuncAttributeMaxDynamicSharedMemorySize, CV_SMEM_TOTAL);
    cudaFuncSetAttribute((const void*)k_c1_mma<63>,   cudaFuncAttributeMaxDynamicSharedMemorySize, C1_SMEM_TOTAL);
    cudaFuncSetAttribute((const void*)k_c1_mma<62>,   cudaFuncAttributeMaxDynamicSharedMemorySize, C1_SMEM_TOTAL);
    cudaFuncSetAttribute((const void*)k_fc_mma,       cudaFuncAttributeMaxDynamicSharedMemorySize, FC_SMEM_TOTAL);

    k_img_prep<<<NI, 256>>>(img_embed, W_ri, b_ri);
    k_gen<<<NI*2*2, 256, GEN_SMEM>>>(mk_W, mk_b, wn_g, wn_b);
    k_cap_red<<<NB, 256, CAP_SMEM>>>(cap_embed, W_rt, b_rt, ca_W);

    // block j = 0 (T 64 -> 63)
    k_conv_mma<63><<<dim3(NB/16, NI, 2), 256, CV_SMEM_TOTAL>>>(0);
    k_c1_mma<63><<<dim3(NB/16, NI), 256, C1_SMEM_TOTAL>>>(bn_g, bn_b, c1_b, c1_W, 0);

    // block j = 1 (T 63 -> 62)
    k_conv_mma<62><<<dim3(NB/16, NI, 2), 256, CV_SMEM_TOTAL>>>(1);
    k_c1_mma<62><<<dim3(NB/16, NI), 256, C1_SMEM_TOTAL>>>(bn_g, bn_b, c1_b, c1_W, 1);

    // tensor-core W_fc + max (16 captions/CTA), then normalize + dot
    k_fc_mma<<<dim3(8, NB/16, NI), 256, FC_SMEM_TOTAL>>>(W_fc, b_fc);
    k_final<<<dim3(NB, NI), 256>>>(out);
}